// round 1
// baseline (speedup 1.0000x reference)
#include <cuda_runtime.h>
#include <math.h>

#define BB   32
#define NN   512
#define FIN  64
#define HH   8
#define HIDD 64
#define OUTD 64

// ---------------- scratch (static device globals; no allocation) ----------------
__device__ float g_Wh   [BB*HH*NN*HIDD];   // 32 MB  Wh[b][h][n][o]
__device__ float g_s1src[BB*HH*NN];
__device__ float g_s1dst[BB*HH*NN];
__device__ float g_x    [BB*NN*HH*HIDD];   // 32 MB  x[b][n][h*64+o]
__device__ float g_Wh2  [BB*NN*OUTD];      // 4 MB
__device__ float g_s2src[BB*NN];
__device__ float g_s2dst[BB*NN];
__device__ float g_SB   [256*513*64];      // suffix sums (positive branch)
__device__ float g_Pb   [256*513*64];      // prefix sums (negative branch)
__device__ float g_z    [BB*NN*OUTD];      // 4 MB
__device__ float g_fc1acc[BB*256];

// ---------------- kernel A: Wh = feat @ W_heads, plus s_src/s_dst dots ----------------
__global__ void kA(const float* __restrict__ state, const float* __restrict__ W_heads,
                   const float* __restrict__ a_src, const float* __restrict__ a_dst) {
    int b = blockIdx.x, h = blockIdx.y;
    __shared__ float sW[64*64];
    __shared__ float sF[64*64];
    __shared__ float sO[64*65];
    __shared__ float sa[64], sdv[64];
    int tid = threadIdx.x;                       // 256
    for (int i = tid; i < 4096; i += 256) sW[i] = W_heads[h*4096 + i];
    if (tid < 64) { sa[tid] = a_src[h*64+tid]; sdv[tid] = a_dst[h*64+tid]; }
    __syncthreads();
    int o = tid & 63, q = tid >> 6;
    for (int nc = 0; nc < 8; nc++) {
        for (int i = tid; i < 4096; i += 256) sF[i] = state[b*32768 + nc*4096 + i];
        __syncthreads();
        for (int r = q; r < 64; r += 4) {
            float acc = 0.f;
            #pragma unroll 16
            for (int f = 0; f < 64; f++) acc += sF[r*64+f] * sW[f*64+o];
            sO[r*65+o] = acc;
            g_Wh[((b*8+h)*512 + nc*64 + r)*64 + o] = acc;
        }
        __syncthreads();
        if (tid < 64) {
            float as = 0.f, ad = 0.f;
            #pragma unroll 16
            for (int o2 = 0; o2 < 64; o2++) { float v = sO[tid*65+o2]; as += v*sa[o2]; ad += v*sdv[o2]; }
            g_s1src[(b*8+h)*512 + nc*64 + tid] = as;
            g_s1dst[(b*8+h)*512 + nc*64 + tid] = ad;
        }
        __syncthreads();
    }
}

// ---------------- GAT attend (both layers): sort + rank-2 prefix trick ----------------
// mode 0: GAT1 over (b,h) blocks -> writes transposed x.  mode 1: GAT2 over b -> writes z.
__global__ void kGAT(int mode) {
    extern __shared__ float sm[];
    float* sWh   = sm;                   // 32768
    float* sd    = sm + 32768;           // 512
    int*   sp    = (int*)(sm + 33280);   // 512
    float* Bv    = sm + 33792;           // 512
    float* bv    = sm + 34304;           // 512
    float* segTB = sm + 34816;           // 8*64
    float* segTb = sm + 35328;           // 8*64
    float* zSB   = sm + 35840;           // 513
    float* zPb   = sm + 36353;           // 513  (total 36866 floats)

    int tid = threadIdx.x;               // 512
    int slot;
    const float *WhG, *ssrcG, *sdstG;
    float* outBase; int outStride, doElu;
    if (mode == 0) {
        int bh = blockIdx.x; slot = bh;
        WhG = g_Wh + bh*32768; ssrcG = g_s1src + bh*512; sdstG = g_s1dst + bh*512;
        int b = bh >> 3, h = bh & 7;
        outBase = g_x + (size_t)(b*512)*512 + h*64; outStride = 512; doElu = 1;
    } else {
        int b = blockIdx.x; slot = b;
        WhG = g_Wh2 + b*32768; ssrcG = g_s2src + b*512; sdstG = g_s2dst + b*512;
        outBase = g_z + b*32768; outStride = 64; doElu = 0;
        if (tid < 256) g_fc1acc[b*256 + tid] = 0.f;   // reset fc1 accumulator
    }
    float* SBg = g_SB + (size_t)slot*513*64;
    float* Pbg = g_Pb + (size_t)slot*513*64;

    for (int i = tid; i < 32768; i += 512) sWh[i] = WhG[i];
    sd[tid] = sdstG[tid]; sp[tid] = tid;
    __syncthreads();

    // bitonic sort ascending on sd (with permutation)
    for (int k = 2; k <= 512; k <<= 1) {
        for (int j = k >> 1; j > 0; j >>= 1) {
            int ixj = tid ^ j;
            if (ixj > tid) {
                float a = sd[tid], c = sd[ixj];
                bool up = ((tid & k) == 0);
                if ((a > c) == up) {
                    sd[tid] = c; sd[ixj] = a;
                    int t2 = sp[tid]; sp[tid] = sp[ixj]; sp[ixj] = t2;
                }
            }
            __syncthreads();
        }
    }
    { float d = sd[tid]; Bv[tid] = expf(d); bv[tid] = expf(0.2f*d); }
    __syncthreads();

    int dim = tid & 63, seg = tid >> 6;
    // pass 1: per-segment totals
    {
        float tb = 0.f, tB = 0.f; int base = seg*64;
        for (int u = 0; u < 64; u++) {
            int t = base + u; float w = sWh[sp[t]*64 + dim];
            tb += bv[t]*w; tB += Bv[t]*w;
        }
        segTb[seg*64+dim] = tb; segTB[seg*64+dim] = tB;
    }
    __syncthreads();
    // pass 2: write exclusive-prefix (neg branch) and inclusive-suffix (pos branch)
    {
        float offb = 0.f, offB = 0.f;
        for (int s2 = 0; s2 < seg; s2++)      offb += segTb[s2*64+dim];
        for (int s2 = seg+1; s2 < 8; s2++)    offB += segTB[s2*64+dim];
        int base = seg*64;
        float acc = offb;
        for (int u = 0; u < 64; u++) {
            int t = base + u;
            Pbg[t*64+dim] = acc;
            acc += bv[t]*sWh[sp[t]*64 + dim];
        }
        if (seg == 7) Pbg[512*64+dim] = acc;
        acc = offB;
        for (int u = 63; u >= 0; u--) {
            int t = base + u;
            acc += Bv[t]*sWh[sp[t]*64 + dim];
            SBg[t*64+dim] = acc;
        }
        if (seg == 7) SBg[512*64+dim] = 0.f;
    }
    __syncthreads();
    // scalar scans (normalizer Z), reuse segTb[0..15] as totals
    if (tid < 16) {
        int which = tid >> 3, sg = tid & 7; float acc = 0.f;
        for (int u = 0; u < 64; u++) { int t = sg*64+u; acc += which ? Bv[t] : bv[t]; }
        segTb[tid] = acc;
    }
    __syncthreads();
    if (tid < 16) {
        int which = tid >> 3, sg = tid & 7; float acc = 0.f;
        if (which == 0) {
            for (int s2 = 0; s2 < sg; s2++) acc += segTb[s2];
            for (int u = 0; u < 64; u++) { int t = sg*64+u; zPb[t] = acc; acc += bv[t]; }
            if (sg == 7) zPb[512] = acc;
        } else {
            for (int s2 = sg+1; s2 < 8; s2++) acc += segTb[8+s2];
            for (int u = 63; u >= 0; u--) { int t = sg*64+u; acc += Bv[t]; zSB[t] = acc; }
            if (sg == 7) zSB[512] = 0.f;
        }
    }
    __syncthreads();

    // row phase: binary search threshold, combine rank-2 terms
    int ig = tid >> 6;
    for (int r = 0; r < 64; r++) {
        int i = r*8 + ig;
        float s = ssrcG[i];
        float thr = -s;
        int lo = 0, hi = 512;
        while (lo < hi) { int mid = (lo+hi) >> 1; if (sd[mid] > thr) hi = mid; else lo = mid+1; }
        int m = lo;
        float A = expf(s), aa = expf(0.2f*s);
        float Z = A*zSB[m] + aa*zPb[m];
        float num = A*SBg[m*64+dim] + aa*Pbg[m*64+dim];
        float v = num / Z;
        if (doElu) v = (v > 0.f) ? v : (expf(v) - 1.f);
        outBase[(size_t)i*outStride + dim] = v;
    }
}

// ---------------- kernel C: Wh2 = x @ W_out ----------------
__global__ void kC(const float* __restrict__ W_out) {
    int b = blockIdx.x, nc = blockIdx.y;
    __shared__ float sX[64*64];
    __shared__ float sW[64*64];
    int tid = threadIdx.x;          // 256
    int o = tid & 63, q = tid >> 6;
    float acc[16];
    #pragma unroll
    for (int ri = 0; ri < 16; ri++) acc[ri] = 0.f;
    for (int kc = 0; kc < 8; kc++) {
        for (int i = tid; i < 4096; i += 256) {
            int n = i >> 6, f = i & 63;
            sX[i] = g_x[(size_t)(b*512 + nc*64 + n)*512 + kc*64 + f];
            sW[i] = W_out[kc*4096 + i];
        }
        __syncthreads();
        #pragma unroll 2
        for (int ri = 0; ri < 16; ri++) {
            int r = q + 4*ri;
            float a2 = acc[ri];
            #pragma unroll 16
            for (int f = 0; f < 64; f++) a2 += sX[r*64+f] * sW[f*64+o];
            acc[ri] = a2;
        }
        __syncthreads();
    }
    #pragma unroll
    for (int ri = 0; ri < 16; ri++)
        g_Wh2[(size_t)(b*512 + nc*64 + q + 4*ri)*64 + o] = acc[ri];
}

// ---------------- kernel C2: s2 dots ----------------
__global__ void kC2(const float* __restrict__ aos, const float* __restrict__ aod) {
    __shared__ float s_as[64], s_ad[64];
    int tid = threadIdx.x;
    if (tid < 64) { s_as[tid] = aos[tid]; s_ad[tid] = aod[tid]; }
    __syncthreads();
    int row = blockIdx.x*256 + tid;          // 16384 rows
    const float* wr = &g_Wh2[(size_t)row*64];
    float as = 0.f, ad = 0.f;
    #pragma unroll 16
    for (int o = 0; o < 64; o++) { float v = wr[o]; as += v*s_as[o]; ad += v*s_ad[o]; }
    g_s2src[row] = as; g_s2dst[row] = ad;
}

// ---------------- kernel E: fc1 split-K with atomics ----------------
__global__ void kE(const float* __restrict__ fc1_w) {
    int ks = blockIdx.x;                 // 128 k-splits of 256
    int k0 = ks * 256;
    __shared__ float sZ[32*33];
    __shared__ __align__(16) float sW[32*256];
    int tid = threadIdx.x;               // 256
    int c4 = tid & 63, rq = tid >> 6;
    float acc[8][4];
    #pragma unroll
    for (int j = 0; j < 8; j++)
        #pragma unroll
        for (int cc = 0; cc < 4; cc++) acc[j][cc] = 0.f;
    for (int kt = 0; kt < 8; kt++) {
        int kb = k0 + kt*32;
        __syncthreads();
        for (int i = tid; i < 1024; i += 256) { int r = i >> 5, kk = i & 31; sZ[r*33+kk] = g_z[(size_t)r*32768 + kb + kk]; }
        for (int i = tid; i < 8192; i += 256) { int kk = i >> 8, c = i & 255; sW[kk*256+c] = fc1_w[(size_t)(kb+kk)*256 + c]; }
        __syncthreads();
        #pragma unroll 4
        for (int kk = 0; kk < 32; kk++) {
            float4 w = *(const float4*)&sW[kk*256 + c4*4];
            #pragma unroll
            for (int j = 0; j < 8; j++) {
                float zz = sZ[(rq + 4*j)*33 + kk];
                acc[j][0] += zz*w.x; acc[j][1] += zz*w.y; acc[j][2] += zz*w.z; acc[j][3] += zz*w.w;
            }
        }
    }
    #pragma unroll
    for (int j = 0; j < 8; j++)
        #pragma unroll
        for (int cc = 0; cc < 4; cc++)
            atomicAdd(&g_fc1acc[(rq + 4*j)*256 + c4*4 + cc], acc[j][cc]);
}

// ---------------- kernel F: bias+relu, fc2, fc3, tanh ----------------
__global__ void kF(const float* __restrict__ fc1_b, const float* __restrict__ fc2_w,
                   const float* __restrict__ fc2_b, const float* __restrict__ fc3_w,
                   const float* __restrict__ fc3_b, float* __restrict__ out) {
    int b = blockIdx.x; int tid = threadIdx.x;   // 256
    __shared__ float s1[256], s2[256];
    s1[tid] = fmaxf(g_fc1acc[b*256 + tid] + fc1_b[tid], 0.f);
    __syncthreads();
    float acc = fc2_b[tid];
    #pragma unroll 8
    for (int k2 = 0; k2 < 256; k2++) acc += s1[k2] * fc2_w[k2*256 + tid];
    s2[tid] = fmaxf(acc, 0.f);
    __syncthreads();
    if (tid < 4) {
        float a3 = fc3_b[tid];
        for (int k2 = 0; k2 < 256; k2++) a3 += s2[k2] * fc3_w[k2*4 + tid];
        out[b*4 + tid] = tanhf(a3);   // MAX_ACTION = 1.0
    }
}

extern "C" void kernel_launch(void* const* d_in, const int* in_sizes, int n_in,
                              void* d_out, int out_size) {
    const float* state     = (const float*)d_in[0];
    const float* W_heads   = (const float*)d_in[1];
    const float* a_src     = (const float*)d_in[2];
    const float* a_dst     = (const float*)d_in[3];
    const float* W_out     = (const float*)d_in[4];
    const float* a_out_src = (const float*)d_in[5];
    const float* a_out_dst = (const float*)d_in[6];
    const float* fc1_w     = (const float*)d_in[7];
    const float* fc1_b     = (const float*)d_in[8];
    const float* fc2_w     = (const float*)d_in[9];
    const float* fc2_b     = (const float*)d_in[10];
    const float* fc3_w     = (const float*)d_in[11];
    const float* fc3_b     = (const float*)d_in[12];
    float* out = (float*)d_out;

    const int SMEM_GAT = 36866 * 4;
    cudaFuncSetAttribute(kGAT, cudaFuncAttributeMaxDynamicSharedMemorySize, SMEM_GAT);

    kA  <<<dim3(32, 8), 256>>>(state, W_heads, a_src, a_dst);
    kGAT<<<256, 512, SMEM_GAT>>>(0);
    kC  <<<dim3(32, 8), 256>>>(W_out);
    kC2 <<<64, 256>>>(a_out_src, a_out_dst);
    kGAT<<<32, 512, SMEM_GAT>>>(1);
    kE  <<<128, 256>>>(fc1_w);
    kF  <<<32, 256>>>(fc1_b, fc2_w, fc2_b, fc3_w, fc3_b, out);
}

// round 3
// speedup vs baseline: 2.0689x; 2.0689x over previous
#include <cuda_runtime.h>
#include <math.h>

#define BB 32

// ---------------- scratch ----------------
__device__ float g_x    [BB*512*512];   // x[b][n][h*64+o]
__device__ float g_Wh2  [BB*512*64];
__device__ float g_s2src[BB*512];
__device__ float g_s2dst[BB*512];
__device__ float g_z    [BB*512*64];
__device__ float g_fc1acc[BB*256];

// ================= kG1: fused feat@W_heads + GAT layer1 (per b,h) =================
// smem floats: sWh 32768 | work 12288 | sd,Bv,bv,ssrc,rA,ra,rIZ 7*512 |
//              sp,rIdx,rm (int) 3*512 | cum 514 cnt 513 (int) | segT 1024 |
//              zSB 513 zPb 513 ztot 16
#define G1_SMEM_FLOATS (32768 + 12288 + 3584 + 1536 + 1027 + 1024 + 1026 + 16)

__global__ __launch_bounds__(512) void kG1(const float* __restrict__ state,
                                           const float* __restrict__ W_heads,
                                           const float* __restrict__ a_src,
                                           const float* __restrict__ a_dst) {
    extern __shared__ float sm[];
    float* sWh  = sm;                 // 32768
    float* work = sm + 32768;         // 12288
    float* sd   = sm + 45056;
    float* Bv   = sd + 512;
    float* bv   = Bv + 512;
    float* ssrc = bv + 512;
    float* rA   = ssrc + 512;
    float* ra   = rA + 512;
    float* rIZ  = ra + 512;
    int*   sp   = (int*)(rIZ + 512);
    int*   rIdx = sp + 512;
    int*   rm   = rIdx + 512;
    int*   cum  = rm + 512;           // 514
    int*   cnt  = cum + 514;          // 513
    float* segT = (float*)(cnt + 513);// 1024
    float* zSB  = segT + 1024;        // 513
    float* zPb  = zSB + 513;          // 513
    float* ztot = zPb + 513;          // 16

    int tid = threadIdx.x;
    int b = blockIdx.x >> 3, h = blockIdx.x & 7;
    float* sW = work;
    float* sF = work + 4096;

    // load W_heads[h] (64x64)
    for (int i = tid; i < 1024; i += 512)
        ((float4*)sW)[i] = ((const float4*)(W_heads + h*4096))[i];

    int tc = tid & 15, tr = tid >> 4;      // tc 0..15, tr 0..31
    int c0 = tc*4, r0 = tr*4;
    // GEMM: Wh[n][o], n in 4 groups of 128 rows
    for (int cc = 0; cc < 4; cc++) {
        __syncthreads();
        for (int i = tid; i < 2048; i += 512)
            ((float4*)sF)[i] = ((const float4*)(state + (size_t)b*32768 + cc*8192))[i];
        __syncthreads();
        float4 a0 = {0,0,0,0}, a1 = a0, a2 = a0, a3 = a0;
        #pragma unroll 8
        for (int f = 0; f < 64; f++) {
            float4 w = ((float4*)(sW + f*64))[tc];
            float x0 = sF[(r0+0)*64+f];
            float x1 = sF[(r0+1)*64+f];
            float x2 = sF[(r0+2)*64+f];
            float x3 = sF[(r0+3)*64+f];
            a0.x += x0*w.x; a0.y += x0*w.y; a0.z += x0*w.z; a0.w += x0*w.w;
            a1.x += x1*w.x; a1.y += x1*w.y; a1.z += x1*w.z; a1.w += x1*w.w;
            a2.x += x2*w.x; a2.y += x2*w.y; a2.z += x2*w.z; a2.w += x2*w.w;
            a3.x += x3*w.x; a3.y += x3*w.y; a3.z += x3*w.z; a3.w += x3*w.w;
        }
        int nb = cc*128 + r0;
        ((float4*)(sWh + (nb+0)*64))[tc] = a0;
        ((float4*)(sWh + (nb+1)*64))[tc] = a1;
        ((float4*)(sWh + (nb+2)*64))[tc] = a2;
        ((float4*)(sWh + (nb+3)*64))[tc] = a3;
    }
    __syncthreads();

    // s_src / s_dst via warp-shuffle row dots
    {
        int w = tid >> 5, lane = tid & 31;
        float as0 = a_src[h*64+lane], as1 = a_src[h*64+32+lane];
        float ad0 = a_dst[h*64+lane], ad1 = a_dst[h*64+32+lane];
        for (int n = w*32; n < w*32+32; n++) {
            float v0 = sWh[n*64+lane], v1 = sWh[n*64+32+lane];
            float ss = v0*as0 + v1*as1;
            float dd = v0*ad0 + v1*ad1;
            #pragma unroll
            for (int off = 16; off; off >>= 1) {
                ss += __shfl_xor_sync(0xffffffffu, ss, off);
                dd += __shfl_xor_sync(0xffffffffu, dd, off);
            }
            if (lane == 0) { ssrc[n] = ss; sd[n] = dd; }
        }
    }
    sp[tid] = tid;
    __syncthreads();

    // bitonic sort ascending on sd with permutation sp
    for (int k = 2; k <= 512; k <<= 1) {
        for (int j = k >> 1; j > 0; j >>= 1) {
            int ixj = tid ^ j;
            if (ixj > tid) {
                float a = sd[tid], c = sd[ixj];
                bool up = ((tid & k) == 0);
                if ((a > c) == up) {
                    sd[tid] = c; sd[ixj] = a;
                    int t2 = sp[tid]; sp[tid] = sp[ixj]; sp[ixj] = t2;
                }
            }
            __syncthreads();
        }
    }
    { float d = sd[tid]; Bv[tid] = expf(d); bv[tid] = expf(0.2f*d); }
    cnt[tid] = 0; if (tid == 0) cnt[512] = 0;
    __syncthreads();

    // scalar normalizer tables
    if (tid < 16) {
        int which = tid >> 3, sg = tid & 7; float acc = 0.f;
        for (int u = 0; u < 64; u++) { int t = sg*64+u; acc += which ? Bv[t] : bv[t]; }
        ztot[tid] = acc;
    }
    __syncthreads();
    if (tid < 16) {
        int which = tid >> 3, sg = tid & 7; float acc = 0.f;
        if (!which) {
            for (int s2 = 0; s2 < sg; s2++) acc += ztot[s2];
            for (int u = 0; u < 64; u++) { int t = sg*64+u; zPb[t] = acc; acc += bv[t]; }
            if (sg == 7) zPb[512] = acc;
        } else {
            for (int s2 = sg+1; s2 < 8; s2++) acc += ztot[8+s2];
            for (int u = 63; u >= 0; u--) { int t = sg*64+u; acc += Bv[t]; zSB[t] = acc; }
            if (sg == 7) zSB[512] = 0.f;
        }
    }
    __syncthreads();

    // per-row: threshold index m, exp factors, 1/Z; histogram of m
    {
        float s = ssrc[tid], thr = -s;
        int lo = 0, hi = 512;
        while (lo < hi) { int mid = (lo+hi) >> 1; if (sd[mid] > thr) hi = mid; else lo = mid+1; }
        int m = lo;
        float A = expf(s), af = expf(0.2f*s);
        rA[tid] = A; ra[tid] = af;
        rIZ[tid] = 1.f / (A*zSB[m] + af*zPb[m]);
        rm[tid] = m;
        atomicAdd(&cnt[m], 1);
    }
    __syncthreads();
    // exclusive scan of cnt -> cum (warp 0)
    if (tid < 32) {
        int start = tid*17, end = min(513, start+17);
        int s = 0;
        for (int i = start; i < end; i++) s += cnt[i];
        int v = s;
        #pragma unroll
        for (int off = 1; off < 32; off <<= 1) {
            int u = __shfl_up_sync(0xffffffffu, v, off);
            if (tid >= off) v += u;
        }
        int run = v - s;
        for (int i = start; i < end; i++) { cum[i] = run; run += cnt[i]; }
        if (start < 513 && end == 513) cum[513] = run;
    }
    __syncthreads();
    cnt[tid] = 0; if (tid == 0) cnt[512] = 0;
    __syncthreads();
    { int m = rm[tid]; int pos = cum[m] + atomicAdd(&cnt[m], 1); rIdx[pos] = tid; }
    __syncthreads();

    int dim = tid & 63, seg = tid >> 6;
    // pass 1: segment totals
    {
        float tB = 0.f, tb = 0.f; int base = seg*64;
        #pragma unroll 8
        for (int u = 0; u < 64; u++) {
            int t = base + u; float w = sWh[sp[t]*64 + dim];
            tB += Bv[t]*w; tb += bv[t]*w;
        }
        segT[seg*64+dim] = tB; segT[512+seg*64+dim] = tb;
    }
    __syncthreads();
    // pass 2: backward suffix scan with fused row emission
    {
        float* outB = g_x + (size_t)b*262144 + h*64;
        float accB = 0.f, accb = 0.f, tTb = 0.f;
        for (int s2 = 0; s2 < 8; s2++) {
            float vB = segT[s2*64+dim], vb = segT[512+s2*64+dim];
            if (s2 > seg) { accB += vB; accb += vb; }
            tTb += vb;
        }
        if (seg == 7) {
            for (int idx = cum[512]; idx < cum[513]; idx++) {
                int r = rIdx[idx];
                float val = (rA[r]*accB + ra[r]*(tTb - accb)) * rIZ[r];
                val = val > 0.f ? val : expf(val) - 1.f;
                outB[r*512 + dim] = val;
            }
        }
        int base = seg*64;
        for (int u = 63; u >= 0; u--) {
            int t = base + u;
            float w = sWh[sp[t]*64 + dim];
            accB += Bv[t]*w; accb += bv[t]*w;
            for (int idx = cum[t]; idx < cum[t+1]; idx++) {
                int r = rIdx[idx];
                float val = (rA[r]*accB + ra[r]*(tTb - accb)) * rIZ[r];
                val = val > 0.f ? val : expf(val) - 1.f;
                outB[r*512 + dim] = val;
            }
        }
    }
}

// ================= kC: Wh2 = x @ W_out, fused s2 dots =================
__global__ __launch_bounds__(256) void kC(const float* __restrict__ W_out,
                                          const float* __restrict__ aos,
                                          const float* __restrict__ aod) {
    __shared__ float sX[4096];
    __shared__ float sW[4096];
    int b = blockIdx.x, nc = blockIdx.y;
    int tid = threadIdx.x;
    if (nc == 0) g_fc1acc[b*256 + tid] = 0.f;       // reset fc1 accumulator
    int tc = tid & 15, tr = tid >> 4;               // both 0..15
    int c0 = tc*4, r0 = tr*4;
    float4 a0 = {0,0,0,0}, a1 = a0, a2 = a0, a3 = a0;
    const float* xbase = g_x + (size_t)(b*512 + nc*64)*512;
    for (int kc = 0; kc < 8; kc++) {
        __syncthreads();
        for (int i = tid; i < 1024; i += 256) {
            int n = i >> 4, c4 = i & 15;
            ((float4*)sX)[i] = *(const float4*)(xbase + (size_t)n*512 + kc*64 + c4*4);
        }
        for (int i = tid; i < 1024; i += 256)
            ((float4*)sW)[i] = ((const float4*)(W_out + kc*4096))[i];
        __syncthreads();
        #pragma unroll 8
        for (int f = 0; f < 64; f++) {
            float4 w = ((float4*)(sW + f*64))[tc];
            float x0 = sX[(r0+0)*64+f];
            float x1 = sX[(r0+1)*64+f];
            float x2 = sX[(r0+2)*64+f];
            float x3 = sX[(r0+3)*64+f];
            a0.x += x0*w.x; a0.y += x0*w.y; a0.z += x0*w.z; a0.w += x0*w.w;
            a1.x += x1*w.x; a1.y += x1*w.y; a1.z += x1*w.z; a1.w += x1*w.w;
            a2.x += x2*w.x; a2.y += x2*w.y; a2.z += x2*w.z; a2.w += x2*w.w;
            a3.x += x3*w.x; a3.y += x3*w.y; a3.z += x3*w.z; a3.w += x3*w.w;
        }
    }
    __syncthreads();
    float* sO = sX;
    ((float4*)(sO + (r0+0)*64))[tc] = a0;
    ((float4*)(sO + (r0+1)*64))[tc] = a1;
    ((float4*)(sO + (r0+2)*64))[tc] = a2;
    ((float4*)(sO + (r0+3)*64))[tc] = a3;
    float* wo = g_Wh2 + (size_t)(b*512 + nc*64 + r0)*64;
    ((float4*)(wo +   0))[tc] = a0;
    ((float4*)(wo +  64))[tc] = a1;
    ((float4*)(wo + 128))[tc] = a2;
    ((float4*)(wo + 192))[tc] = a3;
    __syncthreads();
    {
        int w = tid >> 5, lane = tid & 31;
        float as0 = aos[lane], as1 = aos[32+lane];
        float ad0 = aod[lane], ad1 = aod[32+lane];
        for (int n = w*8; n < w*8+8; n++) {
            float v0 = sO[n*64+lane], v1 = sO[n*64+32+lane];
            float ss = v0*as0 + v1*as1;
            float dd = v0*ad0 + v1*ad1;
            #pragma unroll
            for (int off = 16; off; off >>= 1) {
                ss += __shfl_xor_sync(0xffffffffu, ss, off);
                dd += __shfl_xor_sync(0xffffffffu, dd, off);
            }
            if (lane == 0) {
                g_s2src[b*512 + nc*64 + n] = ss;
                g_s2dst[b*512 + nc*64 + n] = dd;
            }
        }
    }
}

// ================= kG2: GAT layer2 (per b, dim-half), merged emission =================
// smem floats: sWh 16384 | sd..rIZ 7*512 | sp,rIdx,rm 1536 | cum 514 cnt 513 |
//              segT 1024 | zSB 513 zPb 513 ztot 32
#define G2_SMEM_FLOATS (16384 + 3584 + 1536 + 1027 + 1024 + 1026 + 32)

__global__ __launch_bounds__(512) void kG2() {
    extern __shared__ float sm[];
    float* sWh  = sm;                 // 16384 : [n][32]
    float* sd   = sm + 16384;
    float* Bv   = sd + 512;
    float* bv   = Bv + 512;
    float* ssrc = bv + 512;
    float* rA   = ssrc + 512;
    float* ra   = rA + 512;
    float* rIZ  = ra + 512;
    int*   sp   = (int*)(rIZ + 512);
    int*   rIdx = sp + 512;
    int*   rm   = rIdx + 512;
    int*   cum  = rm + 512;
    int*   cnt  = cum + 514;
    float* segT = (float*)(cnt + 513); // 1024
    float* zSB  = segT + 1024;
    float* zPb  = zSB + 513;
    float* ztot = zPb + 513;          // 32

    int tid = threadIdx.x;
    int b = blockIdx.x >> 1, half = blockIdx.x & 1;

    for (int i = tid; i < 4096; i += 512) {
        int n = i >> 3, c4 = i & 7;
        ((float4*)sWh)[i] = *(const float4*)(g_Wh2 + (size_t)b*32768 + n*64 + half*32 + c4*4);
    }
    sd[tid]   = g_s2dst[b*512 + tid];
    ssrc[tid] = g_s2src[b*512 + tid];
    sp[tid]   = tid;
    __syncthreads();

    for (int k = 2; k <= 512; k <<= 1) {
        for (int j = k >> 1; j > 0; j >>= 1) {
            int ixj = tid ^ j;
            if (ixj > tid) {
                float a = sd[tid], c = sd[ixj];
                bool up = ((tid & k) == 0);
                if ((a > c) == up) {
                    sd[tid] = c; sd[ixj] = a;
                    int t2 = sp[tid]; sp[tid] = sp[ixj]; sp[ixj] = t2;
                }
            }
            __syncthreads();
        }
    }
    { float d = sd[tid]; Bv[tid] = expf(d); bv[tid] = expf(0.2f*d); }
    cnt[tid] = 0; if (tid == 0) cnt[512] = 0;
    __syncthreads();

    if (tid < 32) {
        int which = tid >> 4, sg = tid & 15; float acc = 0.f;
        for (int u = 0; u < 32; u++) { int t = sg*32+u; acc += which ? Bv[t] : bv[t]; }
        ztot[tid] = acc;
    }
    __syncthreads();
    if (tid < 32) {
        int which = tid >> 4, sg = tid & 15; float acc = 0.f;
        if (!which) {
            for (int s2 = 0; s2 < sg; s2++) acc += ztot[s2];
            for (int u = 0; u < 32; u++) { int t = sg*32+u; zPb[t] = acc; acc += bv[t]; }
            if (sg == 15) zPb[512] = acc;
        } else {
            for (int s2 = sg+1; s2 < 16; s2++) acc += ztot[16+s2];
            for (int u = 31; u >= 0; u--) { int t = sg*32+u; acc += Bv[t]; zSB[t] = acc; }
            if (sg == 15) zSB[512] = 0.f;
        }
    }
    __syncthreads();

    {
        float s = ssrc[tid], thr = -s;
        int lo = 0, hi = 512;
        while (lo < hi) { int mid = (lo+hi) >> 1; if (sd[mid] > thr) hi = mid; else lo = mid+1; }
        int m = lo;
        float A = expf(s), af = expf(0.2f*s);
        rA[tid] = A; ra[tid] = af;
        rIZ[tid] = 1.f / (A*zSB[m] + af*zPb[m]);
        rm[tid] = m;
        atomicAdd(&cnt[m], 1);
    }
    __syncthreads();
    if (tid < 32) {
        int start = tid*17, end = min(513, start+17);
        int s = 0;
        for (int i = start; i < end; i++) s += cnt[i];
        int v = s;
        #pragma unroll
        for (int off = 1; off < 32; off <<= 1) {
            int u = __shfl_up_sync(0xffffffffu, v, off);
            if (tid >= off) v += u;
        }
        int run = v - s;
        for (int i = start; i < end; i++) { cum[i] = run; run += cnt[i]; }
        if (start < 513 && end == 513) cum[513] = run;
    }
    __syncthreads();
    cnt[tid] = 0; if (tid == 0) cnt[512] = 0;
    __syncthreads();
    { int m = rm[tid]; int pos = cum[m] + atomicAdd(&cnt[m], 1); rIdx[pos] = tid; }
    __syncthreads();

    int dim = tid & 31, seg = tid >> 5;     // 16 segments x 32 dims
    {
        float tB = 0.f, tb = 0.f; int base = seg*32;
        #pragma unroll 8
        for (int u = 0; u < 32; u++) {
            int t = base + u; float w = sWh[sp[t]*32 + dim];
            tB += Bv[t]*w; tb += bv[t]*w;
        }
        segT[seg*32+dim] = tB; segT[512+seg*32+dim] = tb;
    }
    __syncthreads();
    {
        float* outB = g_z + (size_t)b*32768 + half*32;
        float accB = 0.f, accb = 0.f, tTb = 0.f;
        for (int s2 = 0; s2 < 16; s2++) {
            float vB = segT[s2*32+dim], vb = segT[512+s2*32+dim];
            if (s2 > seg) { accB += vB; accb += vb; }
            tTb += vb;
        }
        if (seg == 15) {
            for (int idx = cum[512]; idx < cum[513]; idx++) {
                int r = rIdx[idx];
                float val = (rA[r]*accB + ra[r]*(tTb - accb)) * rIZ[r];
                outB[r*64 + dim] = val;
            }
        }
        int base = seg*32;
        for (int u = 31; u >= 0; u--) {
            int t = base + u;
            float w = sWh[sp[t]*32 + dim];
            accB += Bv[t]*w; accb += bv[t]*w;
            for (int idx = cum[t]; idx < cum[t+1]; idx++) {
                int r = rIdx[idx];
                float val = (rA[r]*accB + ra[r]*(tTb - accb)) * rIZ[r];
                outB[r*64 + dim] = val;
            }
        }
    }
}

// ================= kE: fc1 split-K with atomics =================
__global__ __launch_bounds__(256) void kE(const float* __restrict__ fc1_w) {
    int ks = blockIdx.x;
    int k0 = ks * 256;
    __shared__ float sZ[32*33];
    __shared__ __align__(16) float sW[32*256];
    int tid = threadIdx.x;
    int c4 = tid & 63, rq = tid >> 6;
    float acc[8][4];
    #pragma unroll
    for (int j = 0; j < 8; j++)
        #pragma unroll
        for (int cc = 0; cc < 4; cc++) acc[j][cc] = 0.f;
    for (int kt = 0; kt < 8; kt++) {
        int kb = k0 + kt*32;
        __syncthreads();
        for (int i = tid; i < 1024; i += 256) { int r = i >> 5, kk = i & 31; sZ[r*33+kk] = g_z[(size_t)r*32768 + kb + kk]; }
        for (int i = tid; i < 8192; i += 256) { int kk = i >> 8, c = i & 255; sW[kk*256+c] = fc1_w[(size_t)(kb+kk)*256 + c]; }
        __syncthreads();
        #pragma unroll 4
        for (int kk = 0; kk < 32; kk++) {
            float4 w = *(const float4*)&sW[kk*256 + c4*4];
            #pragma unroll
            for (int j = 0; j < 8; j++) {
                float zz = sZ[(rq + 4*j)*33 + kk];
                acc[j][0] += zz*w.x; acc[j][1] += zz*w.y; acc[j][2] += zz*w.z; acc[j][3] += zz*w.w;
            }
        }
    }
    #pragma unroll
    for (int j = 0; j < 8; j++)
        #pragma unroll
        for (int cc = 0; cc < 4; cc++)
            atomicAdd(&g_fc1acc[(rq + 4*j)*256 + c4*4 + cc], acc[j][cc]);
}

// ================= kF: fc1 bias+relu, fc2, fc3, tanh =================
__global__ __launch_bounds__(256) void kF(const float* __restrict__ fc1_b, const float* __restrict__ fc2_w,
                   const float* __restrict__ fc2_b, const float* __restrict__ fc3_w,
                   const float* __restrict__ fc3_b, float* __restrict__ out) {
    int b = blockIdx.x; int tid = threadIdx.x;
    __shared__ float s1[256], s2[256];
    s1[tid] = fmaxf(g_fc1acc[b*256 + tid] + fc1_b[tid], 0.f);
    __syncthreads();
    float acc = fc2_b[tid];
    #pragma unroll 8
    for (int k2 = 0; k2 < 256; k2++) acc += s1[k2] * fc2_w[k2*256 + tid];
    s2[tid] = fmaxf(acc, 0.f);
    __syncthreads();
    if (tid < 4) {
        float a3 = fc3_b[tid];
        for (int k2 = 0; k2 < 256; k2++) a3 += s2[k2] * fc3_w[k2*4 + tid];
        out[b*4 + tid] = tanhf(a3);
    }
}

extern "C" void kernel_launch(void* const* d_in, const int* in_sizes, int n_in,
                              void* d_out, int out_size) {
    const float* state     = (const float*)d_in[0];
    const float* W_heads   = (const float*)d_in[1];
    const float* a_src     = (const float*)d_in[2];
    const float* a_dst     = (const float*)d_in[3];
    const float* W_out     = (const float*)d_in[4];
    const float* a_out_src = (const float*)d_in[5];
    const float* a_out_dst = (const float*)d_in[6];
    const float* fc1_w     = (const float*)d_in[7];
    const float* fc1_b     = (const float*)d_in[8];
    const float* fc2_w     = (const float*)d_in[9];
    const float* fc2_b     = (const float*)d_in[10];
    const float* fc3_w     = (const float*)d_in[11];
    const float* fc3_b     = (const float*)d_in[12];
    float* out = (float*)d_out;

    const int SM1 = G1_SMEM_FLOATS * 4;
    const int SM2 = G2_SMEM_FLOATS * 4;
    static int inited = 0;
    if (!inited) {
        cudaFuncSetAttribute(kG1, cudaFuncAttributeMaxDynamicSharedMemorySize, SM1);
        cudaFuncSetAttribute(kG2, cudaFuncAttributeMaxDynamicSharedMemorySize, SM2);
        inited = 1;
    }

    kG1<<<256, 512, SM1>>>(state, W_heads, a_src, a_dst);
    kC <<<dim3(32, 8), 256>>>(W_out, a_out_src, a_out_dst);
    kG2<<<64, 512, SM2>>>();
    kE <<<128, 256>>>(fc1_w);
    kF <<<32, 256>>>(fc1_b, fc2_w, fc2_b, fc3_w, fc3_b, out);
}

// round 4
// speedup vs baseline: 2.1254x; 1.0273x over previous
#include <cuda_runtime.h>
#include <math.h>

#define BB 32

// ---------------- scratch ----------------
__device__ float g_x    [BB*512*512];   // x[b][n][h*64+o]
__device__ float g_Wh2  [BB*512*64];
__device__ float g_s2src[BB*512];
__device__ float g_s2dst[BB*512];
__device__ float g_z    [BB*512*64];
__device__ float g_part [256*BB*256];   // fc1 split-K partials [split][b*256+c]

// f32x2 packed helpers
__device__ __forceinline__ unsigned long long pk2(float lo, float hi) {
    unsigned long long r;
    asm("mov.b64 %0, {%1, %2};" : "=l"(r) : "f"(lo), "f"(hi));
    return r;
}
__device__ __forceinline__ void upk2(unsigned long long v, float& lo, float& hi) {
    asm("mov.b64 {%0, %1}, %2;" : "=f"(lo), "=f"(hi) : "l"(v));
}
__device__ __forceinline__ unsigned long long fma2(unsigned long long a, unsigned long long b, unsigned long long c) {
    unsigned long long d;
    asm("fma.rn.f32x2 %0, %1, %2, %3;" : "=l"(d) : "l"(a), "l"(b), "l"(c));
    return d;
}

// ================= kG1: fused feat@W_heads + GAT layer1 (per b,h) =================
#define G1_SMEM_FLOATS (32768 + 12288 + 3584 + 1536 + 1027 + 1024 + 1026 + 16)

__global__ __launch_bounds__(512) void kG1(const float* __restrict__ state,
                                           const float* __restrict__ W_heads,
                                           const float* __restrict__ a_src,
                                           const float* __restrict__ a_dst) {
    extern __shared__ float sm[];
    float* sWh  = sm;                 // 32768
    float* work = sm + 32768;         // 12288
    float* sd   = sm + 45056;
    float* Bv   = sd + 512;
    float* bv   = Bv + 512;
    float* ssrc = bv + 512;
    float* rA   = ssrc + 512;
    float* ra   = rA + 512;
    float* rIZ  = ra + 512;
    int*   sp   = (int*)(rIZ + 512);
    int*   rIdx = sp + 512;
    int*   rm   = rIdx + 512;
    int*   cum  = rm + 512;           // 514
    int*   cnt  = cum + 514;          // 513
    float* segT = (float*)(cnt + 513);// 1024
    float* zSB  = segT + 1024;        // 513
    float* zPb  = zSB + 513;          // 513
    float* ztot = zPb + 513;          // 16

    int tid = threadIdx.x;
    int b = blockIdx.x >> 3, h = blockIdx.x & 7;
    float* sW = work;
    float* sF = work + 4096;

    for (int i = tid; i < 1024; i += 512)
        ((float4*)sW)[i] = ((const float4*)(W_heads + h*4096))[i];

    int tc = tid & 15, tr = tid >> 4;
    int r0 = tr*4;
    for (int cc = 0; cc < 4; cc++) {
        __syncthreads();
        for (int i = tid; i < 2048; i += 512)
            ((float4*)sF)[i] = ((const float4*)(state + (size_t)b*32768 + cc*8192))[i];
        __syncthreads();
        float4 a0 = {0,0,0,0}, a1 = a0, a2 = a0, a3 = a0;
        #pragma unroll 8
        for (int f = 0; f < 64; f++) {
            float4 w = ((float4*)(sW + f*64))[tc];
            float x0 = sF[(r0+0)*64+f];
            float x1 = sF[(r0+1)*64+f];
            float x2 = sF[(r0+2)*64+f];
            float x3 = sF[(r0+3)*64+f];
            a0.x += x0*w.x; a0.y += x0*w.y; a0.z += x0*w.z; a0.w += x0*w.w;
            a1.x += x1*w.x; a1.y += x1*w.y; a1.z += x1*w.z; a1.w += x1*w.w;
            a2.x += x2*w.x; a2.y += x2*w.y; a2.z += x2*w.z; a2.w += x2*w.w;
            a3.x += x3*w.x; a3.y += x3*w.y; a3.z += x3*w.z; a3.w += x3*w.w;
        }
        int nb = cc*128 + r0;
        ((float4*)(sWh + (nb+0)*64))[tc] = a0;
        ((float4*)(sWh + (nb+1)*64))[tc] = a1;
        ((float4*)(sWh + (nb+2)*64))[tc] = a2;
        ((float4*)(sWh + (nb+3)*64))[tc] = a3;
    }
    __syncthreads();

    {
        int w = tid >> 5, lane = tid & 31;
        float as0 = a_src[h*64+lane], as1 = a_src[h*64+32+lane];
        float ad0 = a_dst[h*64+lane], ad1 = a_dst[h*64+32+lane];
        for (int n = w*32; n < w*32+32; n++) {
            float v0 = sWh[n*64+lane], v1 = sWh[n*64+32+lane];
            float ss = v0*as0 + v1*as1;
            float dd = v0*ad0 + v1*ad1;
            #pragma unroll
            for (int off = 16; off; off >>= 1) {
                ss += __shfl_xor_sync(0xffffffffu, ss, off);
                dd += __shfl_xor_sync(0xffffffffu, dd, off);
            }
            if (lane == 0) { ssrc[n] = ss; sd[n] = dd; }
        }
    }
    sp[tid] = tid;
    __syncthreads();

    for (int k = 2; k <= 512; k <<= 1) {
        for (int j = k >> 1; j > 0; j >>= 1) {
            int ixj = tid ^ j;
            if (ixj > tid) {
                float a = sd[tid], c = sd[ixj];
                bool up = ((tid & k) == 0);
                if ((a > c) == up) {
                    sd[tid] = c; sd[ixj] = a;
                    int t2 = sp[tid]; sp[tid] = sp[ixj]; sp[ixj] = t2;
                }
            }
            __syncthreads();
        }
    }
    { float d = sd[tid]; Bv[tid] = expf(d); bv[tid] = expf(0.2f*d); }
    cnt[tid] = 0; if (tid == 0) cnt[512] = 0;
    __syncthreads();

    if (tid < 16) {
        int which = tid >> 3, sg = tid & 7; float acc = 0.f;
        for (int u = 0; u < 64; u++) { int t = sg*64+u; acc += which ? Bv[t] : bv[t]; }
        ztot[tid] = acc;
    }
    __syncthreads();
    if (tid < 16) {
        int which = tid >> 3, sg = tid & 7; float acc = 0.f;
        if (!which) {
            for (int s2 = 0; s2 < sg; s2++) acc += ztot[s2];
            for (int u = 0; u < 64; u++) { int t = sg*64+u; zPb[t] = acc; acc += bv[t]; }
            if (sg == 7) zPb[512] = acc;
        } else {
            for (int s2 = sg+1; s2 < 8; s2++) acc += ztot[8+s2];
            for (int u = 63; u >= 0; u--) { int t = sg*64+u; acc += Bv[t]; zSB[t] = acc; }
            if (sg == 7) zSB[512] = 0.f;
        }
    }
    __syncthreads();

    {
        float s = ssrc[tid], thr = -s;
        int lo = 0, hi = 512;
        while (lo < hi) { int mid = (lo+hi) >> 1; if (sd[mid] > thr) hi = mid; else lo = mid+1; }
        int m = lo;
        float A = expf(s), af = expf(0.2f*s);
        rA[tid] = A; ra[tid] = af;
        rIZ[tid] = 1.f / (A*zSB[m] + af*zPb[m]);
        rm[tid] = m;
        atomicAdd(&cnt[m], 1);
    }
    __syncthreads();
    if (tid < 32) {
        int start = tid*17, end = min(513, start+17);
        int s = 0;
        for (int i = start; i < end; i++) s += cnt[i];
        int v = s;
        #pragma unroll
        for (int off = 1; off < 32; off <<= 1) {
            int u = __shfl_up_sync(0xffffffffu, v, off);
            if (tid >= off) v += u;
        }
        int run = v - s;
        for (int i = start; i < end; i++) { cum[i] = run; run += cnt[i]; }
        if (start < 513 && end == 513) cum[513] = run;
    }
    __syncthreads();
    cnt[tid] = 0; if (tid == 0) cnt[512] = 0;
    __syncthreads();
    { int m = rm[tid]; int pos = cum[m] + atomicAdd(&cnt[m], 1); rIdx[pos] = tid; }
    __syncthreads();

    int dim = tid & 63, seg = tid >> 6;
    {
        float tB = 0.f, tb = 0.f; int base = seg*64;
        #pragma unroll 8
        for (int u = 0; u < 64; u++) {
            int t = base + u; float w = sWh[sp[t]*64 + dim];
            tB += Bv[t]*w; tb += bv[t]*w;
        }
        segT[seg*64+dim] = tB; segT[512+seg*64+dim] = tb;
    }
    __syncthreads();
    {
        float* outB = g_x + (size_t)b*262144 + h*64;
        float accB = 0.f, accb = 0.f, tTb = 0.f;
        for (int s2 = 0; s2 < 8; s2++) {
            float vB = segT[s2*64+dim], vb = segT[512+s2*64+dim];
            if (s2 > seg) { accB += vB; accb += vb; }
            tTb += vb;
        }
        if (seg == 7) {
            for (int idx = cum[512]; idx < cum[513]; idx++) {
                int r = rIdx[idx];
                float val = (rA[r]*accB + ra[r]*(tTb - accb)) * rIZ[r];
                val = val > 0.f ? val : expf(val) - 1.f;
                outB[r*512 + dim] = val;
            }
        }
        int base = seg*64;
        for (int u = 63; u >= 0; u--) {
            int t = base + u;
            float w = sWh[sp[t]*64 + dim];
            accB += Bv[t]*w; accb += bv[t]*w;
            for (int idx = cum[t]; idx < cum[t+1]; idx++) {
                int r = rIdx[idx];
                float val = (rA[r]*accB + ra[r]*(tTb - accb)) * rIZ[r];
                val = val > 0.f ? val : expf(val) - 1.f;
                outB[r*512 + dim] = val;
            }
        }
    }
}

// ================= kC: Wh2 = x @ W_out, fused s2 dots =================
__global__ __launch_bounds__(256) void kC(const float* __restrict__ W_out,
                                          const float* __restrict__ aos,
                                          const float* __restrict__ aod) {
    __shared__ float sX[4096];
    __shared__ float sW[4096];
    int b = blockIdx.x, nc = blockIdx.y;
    int tid = threadIdx.x;
    int tc = tid & 15, tr = tid >> 4;
    int r0 = tr*4;
    float4 a0 = {0,0,0,0}, a1 = a0, a2 = a0, a3 = a0;
    const float* xbase = g_x + (size_t)(b*512 + nc*64)*512;
    for (int kc = 0; kc < 8; kc++) {
        __syncthreads();
        for (int i = tid; i < 1024; i += 256) {
            int n = i >> 4, c4 = i & 15;
            ((float4*)sX)[i] = *(const float4*)(xbase + (size_t)n*512 + kc*64 + c4*4);
        }
        for (int i = tid; i < 1024; i += 256)
            ((float4*)sW)[i] = ((const float4*)(W_out + kc*4096))[i];
        __syncthreads();
        #pragma unroll 8
        for (int f = 0; f < 64; f++) {
            float4 w = ((float4*)(sW + f*64))[tc];
            float x0 = sX[(r0+0)*64+f];
            float x1 = sX[(r0+1)*64+f];
            float x2 = sX[(r0+2)*64+f];
            float x3 = sX[(r0+3)*64+f];
            a0.x += x0*w.x; a0.y += x0*w.y; a0.z += x0*w.z; a0.w += x0*w.w;
            a1.x += x1*w.x; a1.y += x1*w.y; a1.z += x1*w.z; a1.w += x1*w.w;
            a2.x += x2*w.x; a2.y += x2*w.y; a2.z += x2*w.z; a2.w += x2*w.w;
            a3.x += x3*w.x; a3.y += x3*w.y; a3.z += x3*w.z; a3.w += x3*w.w;
        }
    }
    __syncthreads();
    float* sO = sX;
    ((float4*)(sO + (r0+0)*64))[tc] = a0;
    ((float4*)(sO + (r0+1)*64))[tc] = a1;
    ((float4*)(sO + (r0+2)*64))[tc] = a2;
    ((float4*)(sO + (r0+3)*64))[tc] = a3;
    float* wo = g_Wh2 + (size_t)(b*512 + nc*64 + r0)*64;
    ((float4*)(wo +   0))[tc] = a0;
    ((float4*)(wo +  64))[tc] = a1;
    ((float4*)(wo + 128))[tc] = a2;
    ((float4*)(wo + 192))[tc] = a3;
    __syncthreads();
    {
        int w = tid >> 5, lane = tid & 31;
        float as0 = aos[lane], as1 = aos[32+lane];
        float ad0 = aod[lane], ad1 = aod[32+lane];
        for (int n = w*8; n < w*8+8; n++) {
            float v0 = sO[n*64+lane], v1 = sO[n*64+32+lane];
            float ss = v0*as0 + v1*as1;
            float dd = v0*ad0 + v1*ad1;
            #pragma unroll
            for (int off = 16; off; off >>= 1) {
                ss += __shfl_xor_sync(0xffffffffu, ss, off);
                dd += __shfl_xor_sync(0xffffffffu, dd, off);
            }
            if (lane == 0) {
                g_s2src[b*512 + nc*64 + n] = ss;
                g_s2dst[b*512 + nc*64 + n] = dd;
            }
        }
    }
}

// ================= kG2: GAT layer2 (per b, dim-half) =================
#define G2_SMEM_FLOATS (16384 + 3584 + 1536 + 1027 + 1024 + 1026 + 32)

__global__ __launch_bounds__(512) void kG2() {
    extern __shared__ float sm[];
    float* sWh  = sm;
    float* sd   = sm + 16384;
    float* Bv   = sd + 512;
    float* bv   = Bv + 512;
    float* ssrc = bv + 512;
    float* rA   = ssrc + 512;
    float* ra   = rA + 512;
    float* rIZ  = ra + 512;
    int*   sp   = (int*)(rIZ + 512);
    int*   rIdx = sp + 512;
    int*   rm   = rIdx + 512;
    int*   cum  = rm + 512;
    int*   cnt  = cum + 514;
    float* segT = (float*)(cnt + 513);
    float* zSB  = segT + 1024;
    float* zPb  = zSB + 513;
    float* ztot = zPb + 513;

    int tid = threadIdx.x;
    int b = blockIdx.x >> 1, half = blockIdx.x & 1;

    for (int i = tid; i < 4096; i += 512) {
        int n = i >> 3, c4 = i & 7;
        ((float4*)sWh)[i] = *(const float4*)(g_Wh2 + (size_t)b*32768 + n*64 + half*32 + c4*4);
    }
    sd[tid]   = g_s2dst[b*512 + tid];
    ssrc[tid] = g_s2src[b*512 + tid];
    sp[tid]   = tid;
    __syncthreads();

    for (int k = 2; k <= 512; k <<= 1) {
        for (int j = k >> 1; j > 0; j >>= 1) {
            int ixj = tid ^ j;
            if (ixj > tid) {
                float a = sd[tid], c = sd[ixj];
                bool up = ((tid & k) == 0);
                if ((a > c) == up) {
                    sd[tid] = c; sd[ixj] = a;
                    int t2 = sp[tid]; sp[tid] = sp[ixj]; sp[ixj] = t2;
                }
            }
            __syncthreads();
        }
    }
    { float d = sd[tid]; Bv[tid] = expf(d); bv[tid] = expf(0.2f*d); }
    cnt[tid] = 0; if (tid == 0) cnt[512] = 0;
    __syncthreads();

    if (tid < 32) {
        int which = tid >> 4, sg = tid & 15; float acc = 0.f;
        for (int u = 0; u < 32; u++) { int t = sg*32+u; acc += which ? Bv[t] : bv[t]; }
        ztot[tid] = acc;
    }
    __syncthreads();
    if (tid < 32) {
        int which = tid >> 4, sg = tid & 15; float acc = 0.f;
        if (!which) {
            for (int s2 = 0; s2 < sg; s2++) acc += ztot[s2];
            for (int u = 0; u < 32; u++) { int t = sg*32+u; zPb[t] = acc; acc += bv[t]; }
            if (sg == 15) zPb[512] = acc;
        } else {
            for (int s2 = sg+1; s2 < 16; s2++) acc += ztot[16+s2];
            for (int u = 31; u >= 0; u--) { int t = sg*32+u; acc += Bv[t]; zSB[t] = acc; }
            if (sg == 15) zSB[512] = 0.f;
        }
    }
    __syncthreads();

    {
        float s = ssrc[tid], thr = -s;
        int lo = 0, hi = 512;
        while (lo < hi) { int mid = (lo+hi) >> 1; if (sd[mid] > thr) hi = mid; else lo = mid+1; }
        int m = lo;
        float A = expf(s), af = expf(0.2f*s);
        rA[tid] = A; ra[tid] = af;
        rIZ[tid] = 1.f / (A*zSB[m] + af*zPb[m]);
        rm[tid] = m;
        atomicAdd(&cnt[m], 1);
    }
    __syncthreads();
    if (tid < 32) {
        int start = tid*17, end = min(513, start+17);
        int s = 0;
        for (int i = start; i < end; i++) s += cnt[i];
        int v = s;
        #pragma unroll
        for (int off = 1; off < 32; off <<= 1) {
            int u = __shfl_up_sync(0xffffffffu, v, off);
            if (tid >= off) v += u;
        }
        int run = v - s;
        for (int i = start; i < end; i++) { cum[i] = run; run += cnt[i]; }
        if (start < 513 && end == 513) cum[513] = run;
    }
    __syncthreads();
    cnt[tid] = 0; if (tid == 0) cnt[512] = 0;
    __syncthreads();
    { int m = rm[tid]; int pos = cum[m] + atomicAdd(&cnt[m], 1); rIdx[pos] = tid; }
    __syncthreads();

    int dim = tid & 31, seg = tid >> 5;
    {
        float tB = 0.f, tb = 0.f; int base = seg*32;
        #pragma unroll 8
        for (int u = 0; u < 32; u++) {
            int t = base + u; float w = sWh[sp[t]*32 + dim];
            tB += Bv[t]*w; tb += bv[t]*w;
        }
        segT[seg*32+dim] = tB; segT[512+seg*32+dim] = tb;
    }
    __syncthreads();
    {
        float* outB = g_z + (size_t)b*32768 + half*32;
        float accB = 0.f, accb = 0.f, tTb = 0.f;
        for (int s2 = 0; s2 < 16; s2++) {
            float vB = segT[s2*32+dim], vb = segT[512+s2*32+dim];
            if (s2 > seg) { accB += vB; accb += vb; }
            tTb += vb;
        }
        if (seg == 15) {
            for (int idx = cum[512]; idx < cum[513]; idx++) {
                int r = rIdx[idx];
                float val = (rA[r]*accB + ra[r]*(tTb - accb)) * rIZ[r];
                outB[r*64 + dim] = val;
            }
        }
        int base = seg*32;
        for (int u = 31; u >= 0; u--) {
            int t = base + u;
            float w = sWh[sp[t]*32 + dim];
            accB += Bv[t]*w; accb += bv[t]*w;
            for (int idx = cum[t]; idx < cum[t+1]; idx++) {
                int r = rIdx[idx];
                float val = (rA[r]*accB + ra[r]*(tTb - accb)) * rIZ[r];
                outB[r*64 + dim] = val;
            }
        }
    }
}

// ================= kE: fc1 split-K streamer (f32x2 packed, no atomics) =================
// grid 256 (k-slice 128 each), 256 threads: tid&127 = column pair (c, c+128),
// tid>>7 = k-half (64 k's). W read once, coalesced, straight from global.
__global__ __launch_bounds__(256) void kE(const float* __restrict__ fc1_w) {
    __shared__ __align__(16) unsigned long long sZd[32*128];   // packed (z,z), 32KB
    int tid = threadIdx.x;
    int split = blockIdx.x;
    int k0 = split * 128;
    int cp = tid & 127, kh = tid >> 7;

    // stage z slice, packed duplicated
    for (int i = tid; i < 4096; i += 256) {
        int r = i >> 7, k = i & 127;
        float v = g_z[(size_t)r*32768 + k0 + k];
        sZd[i] = pk2(v, v);
    }
    __syncthreads();

    unsigned long long acc[32];
    unsigned long long zero = pk2(0.f, 0.f);
    #pragma unroll
    for (int r = 0; r < 32; r++) acc[r] = zero;

    const float* Wp = fc1_w + (size_t)(k0 + kh*64)*256;
    int khbase = kh*64;
    for (int kk = 0; kk < 64; kk += 2) {
        float wa0 = Wp[(size_t)kk*256 + cp];
        float wb0 = Wp[(size_t)kk*256 + cp + 128];
        float wa1 = Wp[(size_t)(kk+1)*256 + cp];
        float wb1 = Wp[(size_t)(kk+1)*256 + cp + 128];
        unsigned long long w0 = pk2(wa0, wb0);
        unsigned long long w1 = pk2(wa1, wb1);
        const ulonglong2* zrow = (const ulonglong2*)&sZd[khbase + kk];
        #pragma unroll
        for (int r = 0; r < 32; r++) {
            ulonglong2 zz = zrow[r*64];          // (r*128 + kk)/2 entries of ulonglong2
            acc[r] = fma2(zz.x, w0, acc[r]);
            acc[r] = fma2(zz.y, w1, acc[r]);
        }
    }
    __syncthreads();

    // merge the two k-halves via smem (reuse sZd)
    float* red = (float*)sZd;                    // 32 rows x 128 cp x 2 floats
    if (kh == 1) {
        #pragma unroll
        for (int r = 0; r < 32; r++) {
            float lo, hi; upk2(acc[r], lo, hi);
            red[(r*128 + cp)*2 + 0] = lo;
            red[(r*128 + cp)*2 + 1] = hi;
        }
    }
    __syncthreads();
    if (kh == 0) {
        float* outp = g_part + (size_t)split*8192;
        #pragma unroll
        for (int r = 0; r < 32; r++) {
            float lo, hi; upk2(acc[r], lo, hi);
            lo += red[(r*128 + cp)*2 + 0];
            hi += red[(r*128 + cp)*2 + 1];
            outp[r*256 + cp]       = lo;
            outp[r*256 + cp + 128] = hi;
        }
    }
}

// ================= kF: reduce partials, bias+relu, fc2, fc3, tanh =================
__global__ __launch_bounds__(256) void kF(const float* __restrict__ fc1_b, const float* __restrict__ fc2_w,
                   const float* __restrict__ fc2_b, const float* __restrict__ fc3_w,
                   const float* __restrict__ fc3_b, float* __restrict__ out) {
    int b = blockIdx.x; int tid = threadIdx.x;
    __shared__ float s1[256], s2[256];
    {
        const float* pp = g_part + b*256 + tid;
        float a0 = 0.f, a1 = 0.f, a2 = 0.f, a3 = 0.f;
        #pragma unroll 4
        for (int s = 0; s < 256; s += 4) {
            a0 += pp[(size_t)(s+0)*8192];
            a1 += pp[(size_t)(s+1)*8192];
            a2 += pp[(size_t)(s+2)*8192];
            a3 += pp[(size_t)(s+3)*8192];
        }
        s1[tid] = fmaxf((a0+a1) + (a2+a3) + fc1_b[tid], 0.f);
    }
    __syncthreads();
    float acc = fc2_b[tid];
    #pragma unroll 8
    for (int k2 = 0; k2 < 256; k2++) acc += s1[k2] * fc2_w[k2*256 + tid];
    s2[tid] = fmaxf(acc, 0.f);
    __syncthreads();
    if (tid < 4) {
        float a3 = fc3_b[tid];
        for (int k2 = 0; k2 < 256; k2++) a3 += s2[k2] * fc3_w[k2*4 + tid];
        out[b*4 + tid] = tanhf(a3);
    }
}

extern "C" void kernel_launch(void* const* d_in, const int* in_sizes, int n_in,
                              void* d_out, int out_size) {
    const float* state     = (const float*)d_in[0];
    const float* W_heads   = (const float*)d_in[1];
    const float* a_src     = (const float*)d_in[2];
    const float* a_dst     = (const float*)d_in[3];
    const float* W_out     = (const float*)d_in[4];
    const float* a_out_src = (const float*)d_in[5];
    const float* a_out_dst = (const float*)d_in[6];
    const float* fc1_w     = (const float*)d_in[7];
    const float* fc1_b     = (const float*)d_in[8];
    const float* fc2_w     = (const float*)d_in[9];
    const float* fc2_b     = (const float*)d_in[10];
    const float* fc3_w     = (const float*)d_in[11];
    const float* fc3_b     = (const float*)d_in[12];
    float* out = (float*)d_out;

    const int SM1 = G1_SMEM_FLOATS * 4;
    const int SM2 = G2_SMEM_FLOATS * 4;
    static int inited = 0;
    if (!inited) {
        cudaFuncSetAttribute(kG1, cudaFuncAttributeMaxDynamicSharedMemorySize, SM1);
        cudaFuncSetAttribute(kG2, cudaFuncAttributeMaxDynamicSharedMemorySize, SM2);
        inited = 1;
    }

    kG1<<<256, 512, SM1>>>(state, W_heads, a_src, a_dst);
    kC <<<dim3(32, 8), 256>>>(W_out, a_out_src, a_out_dst);
    kG2<<<64, 512, SM2>>>();
    kE <<<256, 256>>>(fc1_w);
    kF <<<32, 256>>>(fc1_b, fc2_w, fc2_b, fc3_w, fc3_b, out);
}

// round 7
// speedup vs baseline: 2.2477x; 1.0575x over previous
#include <cuda_runtime.h>
#include <math.h>

#define BB 32

// ---------------- scratch ----------------
__device__ float g_x    [BB*512*512];   // x[b][n][h*64+o]
__device__ float g_Wh2  [BB*512*64];
__device__ float g_s2src[BB*512];
__device__ float g_s2dst[BB*512];
__device__ float g_z    [BB*512*64];
__device__ float g_part [256*BB*256];   // fc1 split-K partials [split][b*256+c]

// f32x2 packed helpers
__device__ __forceinline__ unsigned long long pk2(float lo, float hi) {
    unsigned long long r;
    asm("mov.b64 %0, {%1, %2};" : "=l"(r) : "f"(lo), "f"(hi));
    return r;
}
__device__ __forceinline__ void upk2(unsigned long long v, float& lo, float& hi) {
    asm("mov.b64 {%0, %1}, %2;" : "=f"(lo), "=f"(hi) : "l"(v));
}
__device__ __forceinline__ unsigned long long fma2(unsigned long long a, unsigned long long b, unsigned long long c) {
    unsigned long long d;
    asm("fma.rn.f32x2 %0, %1, %2, %3;" : "=l"(d) : "l"(a), "l"(b), "l"(c));
    return d;
}

// ================= kG1: fused feat@W_heads + GAT layer1 (per b,h) =================
#define G1_SMEM_FLOATS (32768 + 12288 + 3584 + 1536 + 1027 + 1024 + 1026 + 16)

__global__ __launch_bounds__(512) void kG1(const float* __restrict__ state,
                                           const float* __restrict__ W_heads,
                                           const float* __restrict__ a_src,
                                           const float* __restrict__ a_dst) {
    extern __shared__ float sm[];
    float* sWh  = sm;                 // 32768
    float* work = sm + 32768;         // 12288
    float* sd   = sm + 45056;
    float* Bv   = sd + 512;
    float* bv   = Bv + 512;
    float* ssrc = bv + 512;
    float* rA   = ssrc + 512;
    float* ra   = rA + 512;
    float* rIZ  = ra + 512;
    int*   sp   = (int*)(rIZ + 512);
    int*   rIdx = sp + 512;
    int*   rm   = rIdx + 512;
    int*   cum  = rm + 512;           // 514
    int*   cnt  = cum + 514;          // 513
    float* segT = (float*)(cnt + 513);// 1024
    float* zSB  = segT + 1024;        // 513
    float* zPb  = zSB + 513;          // 513
    float* ztot = zPb + 513;          // 16

    int tid = threadIdx.x;
    int b = blockIdx.x >> 3, h = blockIdx.x & 7;
    float* sW = work;
    float* sF = work + 4096;

    for (int i = tid; i < 1024; i += 512)
        ((float4*)sW)[i] = ((const float4*)(W_heads + h*4096))[i];

    int tc = tid & 15, tr = tid >> 4;
    int r0 = tr*4;
    for (int cc = 0; cc < 4; cc++) {
        __syncthreads();
        for (int i = tid; i < 2048; i += 512)
            ((float4*)sF)[i] = ((const float4*)(state + (size_t)b*32768 + cc*8192))[i];
        __syncthreads();
        float4 a0 = {0,0,0,0}, a1 = a0, a2 = a0, a3 = a0;
        #pragma unroll 8
        for (int f = 0; f < 64; f++) {
            float4 w = ((float4*)(sW + f*64))[tc];
            float x0 = sF[(r0+0)*64+f];
            float x1 = sF[(r0+1)*64+f];
            float x2 = sF[(r0+2)*64+f];
            float x3 = sF[(r0+3)*64+f];
            a0.x += x0*w.x; a0.y += x0*w.y; a0.z += x0*w.z; a0.w += x0*w.w;
            a1.x += x1*w.x; a1.y += x1*w.y; a1.z += x1*w.z; a1.w += x1*w.w;
            a2.x += x2*w.x; a2.y += x2*w.y; a2.z += x2*w.z; a2.w += x2*w.w;
            a3.x += x3*w.x; a3.y += x3*w.y; a3.z += x3*w.z; a3.w += x3*w.w;
        }
        int nb = cc*128 + r0;
        ((float4*)(sWh + (nb+0)*64))[tc] = a0;
        ((float4*)(sWh + (nb+1)*64))[tc] = a1;
        ((float4*)(sWh + (nb+2)*64))[tc] = a2;
        ((float4*)(sWh + (nb+3)*64))[tc] = a3;
    }
    __syncthreads();

    {
        int w = tid >> 5, lane = tid & 31;
        float as0 = a_src[h*64+lane], as1 = a_src[h*64+32+lane];
        float ad0 = a_dst[h*64+lane], ad1 = a_dst[h*64+32+lane];
        for (int n = w*32; n < w*32+32; n++) {
            float v0 = sWh[n*64+lane], v1 = sWh[n*64+32+lane];
            float ss = v0*as0 + v1*as1;
            float dd = v0*ad0 + v1*ad1;
            #pragma unroll
            for (int off = 16; off; off >>= 1) {
                ss += __shfl_xor_sync(0xffffffffu, ss, off);
                dd += __shfl_xor_sync(0xffffffffu, dd, off);
            }
            if (lane == 0) { ssrc[n] = ss; sd[n] = dd; }
        }
    }
    sp[tid] = tid;
    __syncthreads();

    for (int k = 2; k <= 512; k <<= 1) {
        for (int j = k >> 1; j > 0; j >>= 1) {
            int ixj = tid ^ j;
            if (ixj > tid) {
                float a = sd[tid], c = sd[ixj];
                bool up = ((tid & k) == 0);
                if ((a > c) == up) {
                    sd[tid] = c; sd[ixj] = a;
                    int t2 = sp[tid]; sp[tid] = sp[ixj]; sp[ixj] = t2;
                }
            }
            __syncthreads();
        }
    }
    { float d = sd[tid]; Bv[tid] = expf(d); bv[tid] = expf(0.2f*d); }
    cnt[tid] = 0; if (tid == 0) cnt[512] = 0;
    __syncthreads();

    if (tid < 16) {
        int which = tid >> 3, sg = tid & 7; float acc = 0.f;
        for (int u = 0; u < 64; u++) { int t = sg*64+u; acc += which ? Bv[t] : bv[t]; }
        ztot[tid] = acc;
    }
    __syncthreads();
    if (tid < 16) {
        int which = tid >> 3, sg = tid & 7; float acc = 0.f;
        if (!which) {
            for (int s2 = 0; s2 < sg; s2++) acc += ztot[s2];
            for (int u = 0; u < 64; u++) { int t = sg*64+u; zPb[t] = acc; acc += bv[t]; }
            if (sg == 7) zPb[512] = acc;
        } else {
            for (int s2 = sg+1; s2 < 8; s2++) acc += ztot[8+s2];
            for (int u = 63; u >= 0; u--) { int t = sg*64+u; acc += Bv[t]; zSB[t] = acc; }
            if (sg == 7) zSB[512] = 0.f;
        }
    }
    __syncthreads();

    {
        float s = ssrc[tid], thr = -s;
        int lo = 0, hi = 512;
        while (lo < hi) { int mid = (lo+hi) >> 1; if (sd[mid] > thr) hi = mid; else lo = mid+1; }
        int m = lo;
        float A = expf(s), af = expf(0.2f*s);
        rA[tid] = A; ra[tid] = af;
        rIZ[tid] = 1.f / (A*zSB[m] + af*zPb[m]);
        rm[tid] = m;
        atomicAdd(&cnt[m], 1);
    }
    __syncthreads();
    if (tid < 32) {
        int start = tid*17, end = min(513, start+17);
        int s = 0;
        for (int i = start; i < end; i++) s += cnt[i];
        int v = s;
        #pragma unroll
        for (int off = 1; off < 32; off <<= 1) {
            int u = __shfl_up_sync(0xffffffffu, v, off);
            if (tid >= off) v += u;
        }
        int run = v - s;
        for (int i = start; i < end; i++) { cum[i] = run; run += cnt[i]; }
        if (start < 513 && end == 513) cum[513] = run;
    }
    __syncthreads();
    cnt[tid] = 0; if (tid == 0) cnt[512] = 0;
    __syncthreads();
    { int m = rm[tid]; int pos = cum[m] + atomicAdd(&cnt[m], 1); rIdx[pos] = tid; }
    __syncthreads();

    int dim = tid & 63, seg = tid >> 6;
    {
        float tB = 0.f, tb = 0.f; int base = seg*64;
        #pragma unroll 8
        for (int u = 0; u < 64; u++) {
            int t = base + u; float w = sWh[sp[t]*64 + dim];
            tB += Bv[t]*w; tb += bv[t]*w;
        }
        segT[seg*64+dim] = tB; segT[512+seg*64+dim] = tb;
    }
    __syncthreads();
    {
        float* outB = g_x + (size_t)b*262144 + h*64;
        float accB = 0.f, accb = 0.f, tTb = 0.f;
        for (int s2 = 0; s2 < 8; s2++) {
            float vB = segT[s2*64+dim], vb = segT[512+s2*64+dim];
            if (s2 > seg) { accB += vB; accb += vb; }
            tTb += vb;
        }
        if (seg == 7) {
            for (int idx = cum[512]; idx < cum[513]; idx++) {
                int r = rIdx[idx];
                float val = (rA[r]*accB + ra[r]*(tTb - accb)) * rIZ[r];
                val = val > 0.f ? val : expf(val) - 1.f;
                outB[r*512 + dim] = val;
            }
        }
        int base = seg*64;
        for (int u = 63; u >= 0; u--) {
            int t = base + u;
            float w = sWh[sp[t]*64 + dim];
            accB += Bv[t]*w; accb += bv[t]*w;
            for (int idx = cum[t]; idx < cum[t+1]; idx++) {
                int r = rIdx[idx];
                float val = (rA[r]*accB + ra[r]*(tTb - accb)) * rIZ[r];
                val = val > 0.f ? val : expf(val) - 1.f;
                outB[r*512 + dim] = val;
            }
        }
    }
}

// ================= kC: Wh2 = x @ W_out, fused s2 dots =================
__global__ __launch_bounds__(256) void kC(const float* __restrict__ W_out,
                                          const float* __restrict__ aos,
                                          const float* __restrict__ aod) {
    __shared__ float sX[4096];
    __shared__ float sW[4096];
    int b = blockIdx.x, nc = blockIdx.y;
    int tid = threadIdx.x;
    int tc = tid & 15, tr = tid >> 4;
    int r0 = tr*4;
    float4 a0 = {0,0,0,0}, a1 = a0, a2 = a0, a3 = a0;
    const float* xbase = g_x + (size_t)(b*512 + nc*64)*512;
    for (int kc = 0; kc < 8; kc++) {
        __syncthreads();
        for (int i = tid; i < 1024; i += 256) {
            int n = i >> 4, c4 = i & 15;
            ((float4*)sX)[i] = *(const float4*)(xbase + (size_t)n*512 + kc*64 + c4*4);
        }
        for (int i = tid; i < 1024; i += 256)
            ((float4*)sW)[i] = ((const float4*)(W_out + kc*4096))[i];
        __syncthreads();
        #pragma unroll 8
        for (int f = 0; f < 64; f++) {
            float4 w = ((float4*)(sW + f*64))[tc];
            float x0 = sX[(r0+0)*64+f];
            float x1 = sX[(r0+1)*64+f];
            float x2 = sX[(r0+2)*64+f];
            float x3 = sX[(r0+3)*64+f];
            a0.x += x0*w.x; a0.y += x0*w.y; a0.z += x0*w.z; a0.w += x0*w.w;
            a1.x += x1*w.x; a1.y += x1*w.y; a1.z += x1*w.z; a1.w += x1*w.w;
            a2.x += x2*w.x; a2.y += x2*w.y; a2.z += x2*w.z; a2.w += x2*w.w;
            a3.x += x3*w.x; a3.y += x3*w.y; a3.z += x3*w.z; a3.w += x3*w.w;
        }
    }
    __syncthreads();
    float* sO = sX;
    ((float4*)(sO + (r0+0)*64))[tc] = a0;
    ((float4*)(sO + (r0+1)*64))[tc] = a1;
    ((float4*)(sO + (r0+2)*64))[tc] = a2;
    ((float4*)(sO + (r0+3)*64))[tc] = a3;
    float* wo = g_Wh2 + (size_t)(b*512 + nc*64 + r0)*64;
    ((float4*)(wo +   0))[tc] = a0;
    ((float4*)(wo +  64))[tc] = a1;
    ((float4*)(wo + 128))[tc] = a2;
    ((float4*)(wo + 192))[tc] = a3;
    __syncthreads();
    {
        int w = tid >> 5, lane = tid & 31;
        float as0 = aos[lane], as1 = aos[32+lane];
        float ad0 = aod[lane], ad1 = aod[32+lane];
        for (int n = w*8; n < w*8+8; n++) {
            float v0 = sO[n*64+lane], v1 = sO[n*64+32+lane];
            float ss = v0*as0 + v1*as1;
            float dd = v0*ad0 + v1*ad1;
            #pragma unroll
            for (int off = 16; off; off >>= 1) {
                ss += __shfl_xor_sync(0xffffffffu, ss, off);
                dd += __shfl_xor_sync(0xffffffffu, dd, off);
            }
            if (lane == 0) {
                g_s2src[b*512 + nc*64 + n] = ss;
                g_s2dst[b*512 + nc*64 + n] = dd;
            }
        }
    }
}

// ================= kG2: GAT layer2 (per b, dim-half) =================
#define G2_SMEM_FLOATS (16384 + 3584 + 1536 + 1027 + 1024 + 1026 + 32)

__global__ __launch_bounds__(512) void kG2() {
    extern __shared__ float sm[];
    float* sWh  = sm;
    float* sd   = sm + 16384;
    float* Bv   = sd + 512;
    float* bv   = Bv + 512;
    float* ssrc = bv + 512;
    float* rA   = ssrc + 512;
    float* ra   = rA + 512;
    float* rIZ  = ra + 512;
    int*   sp   = (int*)(rIZ + 512);
    int*   rIdx = sp + 512;
    int*   rm   = rIdx + 512;
    int*   cum  = rm + 512;
    int*   cnt  = cum + 514;
    float* segT = (float*)(cnt + 513);
    float* zSB  = segT + 1024;
    float* zPb  = zSB + 513;
    float* ztot = zPb + 513;

    int tid = threadIdx.x;
    int b = blockIdx.x >> 1, half = blockIdx.x & 1;

    for (int i = tid; i < 4096; i += 512) {
        int n = i >> 3, c4 = i & 7;
        ((float4*)sWh)[i] = *(const float4*)(g_Wh2 + (size_t)b*32768 + n*64 + half*32 + c4*4);
    }
    sd[tid]   = g_s2dst[b*512 + tid];
    ssrc[tid] = g_s2src[b*512 + tid];
    sp[tid]   = tid;
    __syncthreads();

    for (int k = 2; k <= 512; k <<= 1) {
        for (int j = k >> 1; j > 0; j >>= 1) {
            int ixj = tid ^ j;
            if (ixj > tid) {
                float a = sd[tid], c = sd[ixj];
                bool up = ((tid & k) == 0);
                if ((a > c) == up) {
                    sd[tid] = c; sd[ixj] = a;
                    int t2 = sp[tid]; sp[tid] = sp[ixj]; sp[ixj] = t2;
                }
            }
            __syncthreads();
        }
    }
    { float d = sd[tid]; Bv[tid] = expf(d); bv[tid] = expf(0.2f*d); }
    cnt[tid] = 0; if (tid == 0) cnt[512] = 0;
    __syncthreads();

    if (tid < 32) {
        int which = tid >> 4, sg = tid & 15; float acc = 0.f;
        for (int u = 0; u < 32; u++) { int t = sg*32+u; acc += which ? Bv[t] : bv[t]; }
        ztot[tid] = acc;
    }
    __syncthreads();
    if (tid < 32) {
        int which = tid >> 4, sg = tid & 15; float acc = 0.f;
        if (!which) {
            for (int s2 = 0; s2 < sg; s2++) acc += ztot[s2];
            for (int u = 0; u < 32; u++) { int t = sg*32+u; zPb[t] = acc; acc += bv[t]; }
            if (sg == 15) zPb[512] = acc;
        } else {
            for (int s2 = sg+1; s2 < 16; s2++) acc += ztot[16+s2];
            for (int u = 31; u >= 0; u--) { int t = sg*32+u; acc += Bv[t]; zSB[t] = acc; }
            if (sg == 15) zSB[512] = 0.f;
        }
    }
    __syncthreads();

    {
        float s = ssrc[tid], thr = -s;
        int lo = 0, hi = 512;
        while (lo < hi) { int mid = (lo+hi) >> 1; if (sd[mid] > thr) hi = mid; else lo = mid+1; }
        int m = lo;
        float A = expf(s), af = expf(0.2f*s);
        rA[tid] = A; ra[tid] = af;
        rIZ[tid] = 1.f / (A*zSB[m] + af*zPb[m]);
        rm[tid] = m;
        atomicAdd(&cnt[m], 1);
    }
    __syncthreads();
    if (tid < 32) {
        int start = tid*17, end = min(513, start+17);
        int s = 0;
        for (int i = start; i < end; i++) s += cnt[i];
        int v = s;
        #pragma unroll
        for (int off = 1; off < 32; off <<= 1) {
            int u = __shfl_up_sync(0xffffffffu, v, off);
            if (tid >= off) v += u;
        }
        int run = v - s;
        for (int i = start; i < end; i++) { cum[i] = run; run += cnt[i]; }
        if (start < 513 && end == 513) cum[513] = run;
    }
    __syncthreads();
    cnt[tid] = 0; if (tid == 0) cnt[512] = 0;
    __syncthreads();
    { int m = rm[tid]; int pos = cum[m] + atomicAdd(&cnt[m], 1); rIdx[pos] = tid; }
    __syncthreads();

    int dim = tid & 31, seg = tid >> 5;
    {
        float tB = 0.f, tb = 0.f; int base = seg*32;
        #pragma unroll 8
        for (int u = 0; u < 32; u++) {
            int t = base + u; float w = sWh[sp[t]*32 + dim];
            tB += Bv[t]*w; tb += bv[t]*w;
        }
        segT[seg*32+dim] = tB; segT[512+seg*32+dim] = tb;
    }
    __syncthreads();
    {
        float* outB = g_z + (size_t)b*32768 + half*32;
        float accB = 0.f, accb = 0.f, tTb = 0.f;
        for (int s2 = 0; s2 < 16; s2++) {
            float vB = segT[s2*32+dim], vb = segT[512+s2*32+dim];
            if (s2 > seg) { accB += vB; accb += vb; }
            tTb += vb;
        }
        if (seg == 15) {
            for (int idx = cum[512]; idx < cum[513]; idx++) {
                int r = rIdx[idx];
                float val = (rA[r]*accB + ra[r]*(tTb - accb)) * rIZ[r];
                outB[r*64 + dim] = val;
            }
        }
        int base = seg*32;
        for (int u = 31; u >= 0; u--) {
            int t = base + u;
            float w = sWh[sp[t]*32 + dim];
            accB += Bv[t]*w; accb += bv[t]*w;
            for (int idx = cum[t]; idx < cum[t+1]; idx++) {
                int r = rIdx[idx];
                float val = (rA[r]*accB + ra[r]*(tTb - accb)) * rIZ[r];
                outB[r*64 + dim] = val;
            }
        }
    }
}

// ================= kE: fc1 split-K streamer v2 (low-reg, float4 W, f32x2) =================
// grid 256 (K-slice 128 each), block 256: tid&63 = column quad (4 cols),
// tid>>6 = row-group (8 rows). 16 packed accs = 32 regs.
__global__ __launch_bounds__(256) void kE(const float* __restrict__ fc1_w) {
    __shared__ __align__(16) unsigned long long sZd[32*128];   // packed (z,z), 32KB
    int tid = threadIdx.x;
    int split = blockIdx.x;
    int k0 = split * 128;
    int c4 = (tid & 63) * 4;
    int rg = (tid >> 6) * 8;

    // stage z slice, packed duplicated
    for (int i = tid; i < 4096; i += 256) {
        int r = i >> 7, k = i & 127;
        float v = g_z[(size_t)r*32768 + k0 + k];
        sZd[i] = pk2(v, v);
    }
    __syncthreads();

    unsigned long long acc[8][2];
    unsigned long long zero = pk2(0.f, 0.f);
    #pragma unroll
    for (int r = 0; r < 8; r++) { acc[r][0] = zero; acc[r][1] = zero; }

    const float* Wp = fc1_w + (size_t)k0*256 + c4;
    const unsigned long long* zp = &sZd[rg*128];
    #pragma unroll 4
    for (int k = 0; k < 128; k++) {
        float4 w = *(const float4*)(Wp + (size_t)k*256);
        unsigned long long w01 = pk2(w.x, w.y);
        unsigned long long w23 = pk2(w.z, w.w);
        #pragma unroll
        for (int r = 0; r < 8; r++) {
            unsigned long long zz = zp[r*128 + k];
            acc[r][0] = fma2(zz, w01, acc[r][0]);
            acc[r][1] = fma2(zz, w23, acc[r][1]);
        }
    }

    float* outp = g_part + (size_t)split*8192;
    #pragma unroll
    for (int r = 0; r < 8; r++) {
        float4 v;
        upk2(acc[r][0], v.x, v.y);
        upk2(acc[r][1], v.z, v.w);
        *(float4*)(outp + (rg + r)*256 + c4) = v;
    }
}

// ================= kF: reduce partials, bias+relu, fc2, fc3, tanh =================
__global__ __launch_bounds__(256) void kF(const float* __restrict__ fc1_b, const float* __restrict__ fc2_w,
                   const float* __restrict__ fc2_b, const float* __restrict__ fc3_w,
                   const float* __restrict__ fc3_b, float* __restrict__ out) {
    int b = blockIdx.x; int tid = threadIdx.x;
    __shared__ float s1[256], s2[256];
    {
        const float* pp = g_part + b*256 + tid;
        float a0 = 0.f, a1 = 0.f, a2 = 0.f, a3 = 0.f;
        #pragma unroll 4
        for (int s = 0; s < 256; s += 4) {
            a0 += pp[(size_t)(s+0)*8192];
            a1 += pp[(size_t)(s+1)*8192];
            a2 += pp[(size_t)(s+2)*8192];
            a3 += pp[(size_t)(s+3)*8192];
        }
        s1[tid] = fmaxf((a0+a1) + (a2+a3) + fc1_b[tid], 0.f);
    }
    __syncthreads();
    float acc = fc2_b[tid];
    #pragma unroll 8
    for (int k2 = 0; k2 < 256; k2++) acc += s1[k2] * fc2_w[k2*256 + tid];
    s2[tid] = fmaxf(acc, 0.f);
    __syncthreads();
    if (tid < 4) {
        float a3 = fc3_b[tid];
        for (int k2 = 0; k2 < 256; k2++) a3 += s2[k2] * fc3_w[k2*4 + tid];
        out[b*4 + tid] = tanhf(a3);
    }
}

extern "C" void kernel_launch(void* const* d_in, const int* in_sizes, int n_in,
                              void* d_out, int out_size) {
    const float* state     = (const float*)d_in[0];
    const float* W_heads   = (const float*)d_in[1];
    const float* a_src     = (const float*)d_in[2];
    const float* a_dst     = (const float*)d_in[3];
    const float* W_out     = (const float*)d_in[4];
    const float* a_out_src = (const float*)d_in[5];
    const float* a_out_dst = (const float*)d_in[6];
    const float* fc1_w     = (const float*)d_in[7];
    const float* fc1_b     = (const float*)d_in[8];
    const float* fc2_w     = (const float*)d_in[9];
    const float* fc2_b     = (const float*)d_in[10];
    const float* fc3_w     = (const float*)d_in[11];
    const float* fc3_b     = (const float*)d_in[12];
    float* out = (float*)d_out;

    const int SM1 = G1_SMEM_FLOATS * 4;
    const int SM2 = G2_SMEM_FLOATS * 4;
    static int inited = 0;
    if (!inited) {
        cudaFuncSetAttribute(kG1, cudaFuncAttributeMaxDynamicSharedMemorySize, SM1);
        cudaFuncSetAttribute(kG2, cudaFuncAttributeMaxDynamicSharedMemorySize, SM2);
        inited = 1;
    }

    kG1<<<256, 512, SM1>>>(state, W_heads, a_src, a_dst);
    kC <<<dim3(32, 8), 256>>>(W_out, a_out_src, a_out_dst);
    kG2<<<64, 512, SM2>>>();
    kE <<<256, 256>>>(fc1_w);
    kF <<<32, 256>>>(fc1_b, fc2_w, fc2_b, fc3_w, fc3_b, out);
}

// round 8
// speedup vs baseline: 2.2540x; 1.0028x over previous
#include <cuda_runtime.h>
#include <math.h>

#define BB 32

// ---------------- scratch ----------------
__device__ float g_x    [BB*512*512];   // x[b][n][h*64+o]
__device__ float g_Wh2  [BB*512*64];
__device__ float g_s2src[BB*512];
__device__ float g_s2dst[BB*512];
__device__ float g_z    [BB*512*64];
__device__ float g_part [256*BB*256];   // fc1 split-K partials [split][b*256+c]
__device__ float g_fc1acc[BB*256];

// f32x2 packed helpers
__device__ __forceinline__ unsigned long long pk2(float lo, float hi) {
    unsigned long long r;
    asm("mov.b64 %0, {%1, %2};" : "=l"(r) : "f"(lo), "f"(hi));
    return r;
}
__device__ __forceinline__ void upk2(unsigned long long v, float& lo, float& hi) {
    asm("mov.b64 {%0, %1}, %2;" : "=f"(lo), "=f"(hi) : "l"(v));
}
__device__ __forceinline__ unsigned long long fma2(unsigned long long a, unsigned long long b, unsigned long long c) {
    unsigned long long d;
    asm("fma.rn.f32x2 %0, %1, %2, %3;" : "=l"(d) : "l"(a), "l"(b), "l"(c));
    return d;
}

// ================= kG1: fused feat@W_heads + GAT layer1 (per b,h) =================
#define G1_SMEM_FLOATS (32768 + 12288 + 3584 + 1536 + 1027 + 1024 + 1026 + 16)

__global__ __launch_bounds__(512) void kG1(const float* __restrict__ state,
                                           const float* __restrict__ W_heads,
                                           const float* __restrict__ a_src,
                                           const float* __restrict__ a_dst) {
    extern __shared__ float sm[];
    float* sWh  = sm;                 // 32768
    float* work = sm + 32768;         // 12288
    float* sd   = sm + 45056;
    float* Bv   = sd + 512;
    float* bv   = Bv + 512;
    float* ssrc = bv + 512;
    float* rA   = ssrc + 512;
    float* ra   = rA + 512;
    float* rIZ  = ra + 512;
    int*   sp   = (int*)(rIZ + 512);
    int*   rIdx = sp + 512;
    int*   rm   = rIdx + 512;
    int*   cum  = rm + 512;           // 514
    int*   cnt  = cum + 514;          // 513
    float* segT = (float*)(cnt + 513);// 1024
    float* zSB  = segT + 1024;        // 513
    float* zPb  = zSB + 513;          // 513
    float* ztot = zPb + 513;          // 16

    int tid = threadIdx.x;
    int b = blockIdx.x >> 3, h = blockIdx.x & 7;
    float* sW = work;
    float* sF = work + 4096;

    for (int i = tid; i < 1024; i += 512)
        ((float4*)sW)[i] = ((const float4*)(W_heads + h*4096))[i];

    int tc = tid & 15, tr = tid >> 4;
    int r0 = tr*4;
    for (int cc = 0; cc < 4; cc++) {
        __syncthreads();
        for (int i = tid; i < 2048; i += 512)
            ((float4*)sF)[i] = ((const float4*)(state + (size_t)b*32768 + cc*8192))[i];
        __syncthreads();
        float4 a0 = {0,0,0,0}, a1 = a0, a2 = a0, a3 = a0;
        #pragma unroll 8
        for (int f = 0; f < 64; f++) {
            float4 w = ((float4*)(sW + f*64))[tc];
            float x0 = sF[(r0+0)*64+f];
            float x1 = sF[(r0+1)*64+f];
            float x2 = sF[(r0+2)*64+f];
            float x3 = sF[(r0+3)*64+f];
            a0.x += x0*w.x; a0.y += x0*w.y; a0.z += x0*w.z; a0.w += x0*w.w;
            a1.x += x1*w.x; a1.y += x1*w.y; a1.z += x1*w.z; a1.w += x1*w.w;
            a2.x += x2*w.x; a2.y += x2*w.y; a2.z += x2*w.z; a2.w += x2*w.w;
            a3.x += x3*w.x; a3.y += x3*w.y; a3.z += x3*w.z; a3.w += x3*w.w;
        }
        int nb = cc*128 + r0;
        ((float4*)(sWh + (nb+0)*64))[tc] = a0;
        ((float4*)(sWh + (nb+1)*64))[tc] = a1;
        ((float4*)(sWh + (nb+2)*64))[tc] = a2;
        ((float4*)(sWh + (nb+3)*64))[tc] = a3;
    }
    __syncthreads();

    {
        int w = tid >> 5, lane = tid & 31;
        float as0 = a_src[h*64+lane], as1 = a_src[h*64+32+lane];
        float ad0 = a_dst[h*64+lane], ad1 = a_dst[h*64+32+lane];
        for (int n = w*32; n < w*32+32; n++) {
            float v0 = sWh[n*64+lane], v1 = sWh[n*64+32+lane];
            float ss = v0*as0 + v1*as1;
            float dd = v0*ad0 + v1*ad1;
            #pragma unroll
            for (int off = 16; off; off >>= 1) {
                ss += __shfl_xor_sync(0xffffffffu, ss, off);
                dd += __shfl_xor_sync(0xffffffffu, dd, off);
            }
            if (lane == 0) { ssrc[n] = ss; sd[n] = dd; }
        }
    }
    sp[tid] = tid;
    __syncthreads();

    for (int k = 2; k <= 512; k <<= 1) {
        for (int j = k >> 1; j > 0; j >>= 1) {
            int ixj = tid ^ j;
            if (ixj > tid) {
                float a = sd[tid], c = sd[ixj];
                bool up = ((tid & k) == 0);
                if ((a > c) == up) {
                    sd[tid] = c; sd[ixj] = a;
                    int t2 = sp[tid]; sp[tid] = sp[ixj]; sp[ixj] = t2;
                }
            }
            __syncthreads();
        }
    }
    { float d = sd[tid]; Bv[tid] = expf(d); bv[tid] = expf(0.2f*d); }
    cnt[tid] = 0; if (tid == 0) cnt[512] = 0;
    __syncthreads();

    if (tid < 16) {
        int which = tid >> 3, sg = tid & 7; float acc = 0.f;
        for (int u = 0; u < 64; u++) { int t = sg*64+u; acc += which ? Bv[t] : bv[t]; }
        ztot[tid] = acc;
    }
    __syncthreads();
    if (tid < 16) {
        int which = tid >> 3, sg = tid & 7; float acc = 0.f;
        if (!which) {
            for (int s2 = 0; s2 < sg; s2++) acc += ztot[s2];
            for (int u = 0; u < 64; u++) { int t = sg*64+u; zPb[t] = acc; acc += bv[t]; }
            if (sg == 7) zPb[512] = acc;
        } else {
            for (int s2 = sg+1; s2 < 8; s2++) acc += ztot[8+s2];
            for (int u = 63; u >= 0; u--) { int t = sg*64+u; acc += Bv[t]; zSB[t] = acc; }
            if (sg == 7) zSB[512] = 0.f;
        }
    }
    __syncthreads();

    {
        float s = ssrc[tid], thr = -s;
        int lo = 0, hi = 512;
        while (lo < hi) { int mid = (lo+hi) >> 1; if (sd[mid] > thr) hi = mid; else lo = mid+1; }
        int m = lo;
        float A = expf(s), af = expf(0.2f*s);
        rA[tid] = A; ra[tid] = af;
        rIZ[tid] = 1.f / (A*zSB[m] + af*zPb[m]);
        rm[tid] = m;
        atomicAdd(&cnt[m], 1);
    }
    __syncthreads();
    if (tid < 32) {
        int start = tid*17, end = min(513, start+17);
        int s = 0;
        for (int i = start; i < end; i++) s += cnt[i];
        int v = s;
        #pragma unroll
        for (int off = 1; off < 32; off <<= 1) {
            int u = __shfl_up_sync(0xffffffffu, v, off);
            if (tid >= off) v += u;
        }
        int run = v - s;
        for (int i = start; i < end; i++) { cum[i] = run; run += cnt[i]; }
        if (start < 513 && end == 513) cum[513] = run;
    }
    __syncthreads();
    cnt[tid] = 0; if (tid == 0) cnt[512] = 0;
    __syncthreads();
    { int m = rm[tid]; int pos = cum[m] + atomicAdd(&cnt[m], 1); rIdx[pos] = tid; }
    __syncthreads();

    int dim = tid & 63, seg = tid >> 6;
    {
        float tB = 0.f, tb = 0.f; int base = seg*64;
        #pragma unroll 8
        for (int u = 0; u < 64; u++) {
            int t = base + u; float w = sWh[sp[t]*64 + dim];
            tB += Bv[t]*w; tb += bv[t]*w;
        }
        segT[seg*64+dim] = tB; segT[512+seg*64+dim] = tb;
    }
    __syncthreads();
    {
        float* outB = g_x + (size_t)b*262144 + h*64;
        float accB = 0.f, accb = 0.f, tTb = 0.f;
        for (int s2 = 0; s2 < 8; s2++) {
            float vB = segT[s2*64+dim], vb = segT[512+s2*64+dim];
            if (s2 > seg) { accB += vB; accb += vb; }
            tTb += vb;
        }
        if (seg == 7) {
            for (int idx = cum[512]; idx < cum[513]; idx++) {
                int r = rIdx[idx];
                float val = (rA[r]*accB + ra[r]*(tTb - accb)) * rIZ[r];
                val = val > 0.f ? val : expf(val) - 1.f;
                outB[r*512 + dim] = val;
            }
        }
        int base = seg*64;
        for (int u = 63; u >= 0; u--) {
            int t = base + u;
            float w = sWh[sp[t]*64 + dim];
            accB += Bv[t]*w; accb += bv[t]*w;
            for (int idx = cum[t]; idx < cum[t+1]; idx++) {
                int r = rIdx[idx];
                float val = (rA[r]*accB + ra[r]*(tTb - accb)) * rIZ[r];
                val = val > 0.f ? val : expf(val) - 1.f;
                outB[r*512 + dim] = val;
            }
        }
    }
}

// ================= kC: Wh2 = x @ W_out, fused s2 dots =================
__global__ __launch_bounds__(256) void kC(const float* __restrict__ W_out,
                                          const float* __restrict__ aos,
                                          const float* __restrict__ aod) {
    __shared__ float sX[4096];
    __shared__ float sW[4096];
    int b = blockIdx.x, nc = blockIdx.y;
    int tid = threadIdx.x;
    int tc = tid & 15, tr = tid >> 4;
    int r0 = tr*4;
    float4 a0 = {0,0,0,0}, a1 = a0, a2 = a0, a3 = a0;
    const float* xbase = g_x + (size_t)(b*512 + nc*64)*512;
    for (int kc = 0; kc < 8; kc++) {
        __syncthreads();
        for (int i = tid; i < 1024; i += 256) {
            int n = i >> 4, c4 = i & 15;
            ((float4*)sX)[i] = *(const float4*)(xbase + (size_t)n*512 + kc*64 + c4*4);
        }
        for (int i = tid; i < 1024; i += 256)
            ((float4*)sW)[i] = ((const float4*)(W_out + kc*4096))[i];
        __syncthreads();
        #pragma unroll 8
        for (int f = 0; f < 64; f++) {
            float4 w = ((float4*)(sW + f*64))[tc];
            float x0 = sX[(r0+0)*64+f];
            float x1 = sX[(r0+1)*64+f];
            float x2 = sX[(r0+2)*64+f];
            float x3 = sX[(r0+3)*64+f];
            a0.x += x0*w.x; a0.y += x0*w.y; a0.z += x0*w.z; a0.w += x0*w.w;
            a1.x += x1*w.x; a1.y += x1*w.y; a1.z += x1*w.z; a1.w += x1*w.w;
            a2.x += x2*w.x; a2.y += x2*w.y; a2.z += x2*w.z; a2.w += x2*w.w;
            a3.x += x3*w.x; a3.y += x3*w.y; a3.z += x3*w.z; a3.w += x3*w.w;
        }
    }
    __syncthreads();
    float* sO = sX;
    ((float4*)(sO + (r0+0)*64))[tc] = a0;
    ((float4*)(sO + (r0+1)*64))[tc] = a1;
    ((float4*)(sO + (r0+2)*64))[tc] = a2;
    ((float4*)(sO + (r0+3)*64))[tc] = a3;
    float* wo = g_Wh2 + (size_t)(b*512 + nc*64 + r0)*64;
    ((float4*)(wo +   0))[tc] = a0;
    ((float4*)(wo +  64))[tc] = a1;
    ((float4*)(wo + 128))[tc] = a2;
    ((float4*)(wo + 192))[tc] = a3;
    __syncthreads();
    {
        int w = tid >> 5, lane = tid & 31;
        float as0 = aos[lane], as1 = aos[32+lane];
        float ad0 = aod[lane], ad1 = aod[32+lane];
        for (int n = w*8; n < w*8+8; n++) {
            float v0 = sO[n*64+lane], v1 = sO[n*64+32+lane];
            float ss = v0*as0 + v1*as1;
            float dd = v0*ad0 + v1*ad1;
            #pragma unroll
            for (int off = 16; off; off >>= 1) {
                ss += __shfl_xor_sync(0xffffffffu, ss, off);
                dd += __shfl_xor_sync(0xffffffffu, dd, off);
            }
            if (lane == 0) {
                g_s2src[b*512 + nc*64 + n] = ss;
                g_s2dst[b*512 + nc*64 + n] = dd;
            }
        }
    }
}

// ================= kG2: GAT layer2 (per b, dim-quarter of 16) =================
// smem floats: sWh 8192 | 7*512 | 3*512 int | cum 514 cnt 513 | segT 1024 |
//              zSB 513 zPb 513 ztot 64
#define G2_SMEM_FLOATS (8192 + 3584 + 1536 + 1027 + 1024 + 1026 + 64)

__global__ __launch_bounds__(512) void kG2() {
    extern __shared__ float sm[];
    float* sWh  = sm;                 // 8192 : [n][16]
    float* sd   = sm + 8192;
    float* Bv   = sd + 512;
    float* bv   = Bv + 512;
    float* ssrc = bv + 512;
    float* rA   = ssrc + 512;
    float* ra   = rA + 512;
    float* rIZ  = ra + 512;
    int*   sp   = (int*)(rIZ + 512);
    int*   rIdx = sp + 512;
    int*   rm   = rIdx + 512;
    int*   cum  = rm + 512;
    int*   cnt  = cum + 514;
    float* segT = (float*)(cnt + 513);   // 1024 (32 segs x 16 dims x 2)
    float* zSB  = segT + 1024;
    float* zPb  = zSB + 513;
    float* ztot = zPb + 513;             // 64

    int tid = threadIdx.x;
    int b = blockIdx.x >> 2, q = blockIdx.x & 3;

    for (int i = tid; i < 2048; i += 512) {
        int n = i >> 2, c4 = i & 3;
        ((float4*)sWh)[i] = *(const float4*)(g_Wh2 + (size_t)b*32768 + n*64 + q*16 + c4*4);
    }
    sd[tid]   = g_s2dst[b*512 + tid];
    ssrc[tid] = g_s2src[b*512 + tid];
    sp[tid]   = tid;
    __syncthreads();

    for (int k = 2; k <= 512; k <<= 1) {
        for (int j = k >> 1; j > 0; j >>= 1) {
            int ixj = tid ^ j;
            if (ixj > tid) {
                float a = sd[tid], c = sd[ixj];
                bool up = ((tid & k) == 0);
                if ((a > c) == up) {
                    sd[tid] = c; sd[ixj] = a;
                    int t2 = sp[tid]; sp[tid] = sp[ixj]; sp[ixj] = t2;
                }
            }
            __syncthreads();
        }
    }
    { float d = sd[tid]; Bv[tid] = expf(d); bv[tid] = expf(0.2f*d); }
    cnt[tid] = 0; if (tid == 0) cnt[512] = 0;
    __syncthreads();

    // 32 segments of 16 for normalizer scans
    if (tid < 64) {
        int which = tid >> 5, sg = tid & 31; float acc = 0.f;
        for (int u = 0; u < 16; u++) { int t = sg*16+u; acc += which ? Bv[t] : bv[t]; }
        ztot[which*32 + sg] = acc;
    }
    __syncthreads();
    if (tid < 64) {
        int which = tid >> 5, sg = tid & 31; float acc = 0.f;
        if (!which) {
            for (int s2 = 0; s2 < sg; s2++) acc += ztot[s2];
            for (int u = 0; u < 16; u++) { int t = sg*16+u; zPb[t] = acc; acc += bv[t]; }
            if (sg == 31) zPb[512] = acc;
        } else {
            for (int s2 = sg+1; s2 < 32; s2++) acc += ztot[32+s2];
            for (int u = 15; u >= 0; u--) { int t = sg*16+u; acc += Bv[t]; zSB[t] = acc; }
            if (sg == 31) zSB[512] = 0.f;
        }
    }
    __syncthreads();

    {
        float s = ssrc[tid], thr = -s;
        int lo = 0, hi = 512;
        while (lo < hi) { int mid = (lo+hi) >> 1; if (sd[mid] > thr) hi = mid; else lo = mid+1; }
        int m = lo;
        float A = expf(s), af = expf(0.2f*s);
        rA[tid] = A; ra[tid] = af;
        rIZ[tid] = 1.f / (A*zSB[m] + af*zPb[m]);
        rm[tid] = m;
        atomicAdd(&cnt[m], 1);
    }
    __syncthreads();
    if (tid < 32) {
        int start = tid*17, end = min(513, start+17);
        int s = 0;
        for (int i = start; i < end; i++) s += cnt[i];
        int v = s;
        #pragma unroll
        for (int off = 1; off < 32; off <<= 1) {
            int u = __shfl_up_sync(0xffffffffu, v, off);
            if (tid >= off) v += u;
        }
        int run = v - s;
        for (int i = start; i < end; i++) { cum[i] = run; run += cnt[i]; }
        if (start < 513 && end == 513) cum[513] = run;
    }
    __syncthreads();
    cnt[tid] = 0; if (tid == 0) cnt[512] = 0;
    __syncthreads();
    { int m = rm[tid]; int pos = cum[m] + atomicAdd(&cnt[m], 1); rIdx[pos] = tid; }
    __syncthreads();

    int dim = tid & 15, seg = tid >> 4;     // 32 segments x 16 dims
    {
        float tB = 0.f, tb = 0.f; int base = seg*16;
        #pragma unroll 8
        for (int u = 0; u < 16; u++) {
            int t = base + u; float w = sWh[sp[t]*16 + dim];
            tB += Bv[t]*w; tb += bv[t]*w;
        }
        segT[seg*16+dim] = tB; segT[512+seg*16+dim] = tb;
    }
    __syncthreads();
    {
        float* outB = g_z + (size_t)b*32768 + q*16;
        float accB = 0.f, accb = 0.f, tTb = 0.f;
        for (int s2 = 0; s2 < 32; s2++) {
            float vB = segT[s2*16+dim], vb = segT[512+s2*16+dim];
            if (s2 > seg) { accB += vB; accb += vb; }
            tTb += vb;
        }
        if (seg == 31) {
            for (int idx = cum[512]; idx < cum[513]; idx++) {
                int r = rIdx[idx];
                float val = (rA[r]*accB + ra[r]*(tTb - accb)) * rIZ[r];
                outB[r*64 + dim] = val;
            }
        }
        int base = seg*16;
        for (int u = 15; u >= 0; u--) {
            int t = base + u;
            float w = sWh[sp[t]*16 + dim];
            accB += Bv[t]*w; accb += bv[t]*w;
            for (int idx = cum[t]; idx < cum[t+1]; idx++) {
                int r = rIdx[idx];
                float val = (rA[r]*accB + ra[r]*(tTb - accb)) * rIZ[r];
                outB[r*64 + dim] = val;
            }
        }
    }
}

// ================= kE v4: fc1 split-K x split-rows streamer =================
// grid (256 k-splits x 2 row-halves) = 512 blocks, 256 threads:
// tid&63 = column quad, tid>>6 = row-group of 4 (16 rows per block).
__global__ __launch_bounds__(256) void kE(const float* __restrict__ fc1_w) {
    __shared__ __align__(16) unsigned long long sZd[16*128];   // packed (z,z), 16KB
    int tid = threadIdx.x;
    int split = blockIdx.x >> 1;
    int rh = blockIdx.x & 1;
    int k0 = split * 128;
    int cq = tid & 63;
    int rg = tid >> 6;                  // 0..3

    for (int i = tid; i < 2048; i += 256) {
        int r = i >> 7, k = i & 127;
        float v = g_z[(size_t)(rh*16 + r)*32768 + k0 + k];
        sZd[i] = pk2(v, v);
    }
    __syncthreads();

    unsigned long long acc[4][2];
    unsigned long long zero = pk2(0.f, 0.f);
    #pragma unroll
    for (int r = 0; r < 4; r++) { acc[r][0] = zero; acc[r][1] = zero; }

    const float* Wp = fc1_w + (size_t)k0*256 + cq*4;
    const unsigned long long* zp = &sZd[rg*4*128];
    #pragma unroll 4
    for (int k = 0; k < 128; k++) {
        float4 w = *(const float4*)(Wp + (size_t)k*256);
        unsigned long long w01 = pk2(w.x, w.y);
        unsigned long long w23 = pk2(w.z, w.w);
        #pragma unroll
        for (int r = 0; r < 4; r++) {
            unsigned long long zz = zp[r*128 + k];
            acc[r][0] = fma2(zz, w01, acc[r][0]);
            acc[r][1] = fma2(zz, w23, acc[r][1]);
        }
    }

    float* outp = g_part + (size_t)split*8192 + rh*16*256;
    #pragma unroll
    for (int r = 0; r < 4; r++) {
        float4 v;
        upk2(acc[r][0], v.x, v.y);
        upk2(acc[r][1], v.z, v.w);
        *(float4*)(outp + (rg*4 + r)*256 + cq*4) = v;
    }
}

// ================= kR: reduce 256 split-partials -> g_fc1acc =================
__global__ __launch_bounds__(256) void kR() {
    __shared__ float red[256];
    int b = blockIdx.x >> 3, cs = blockIdx.x & 7;
    int tid = threadIdx.x;
    int cl = tid & 31, sg = tid >> 5;
    const float* pp = g_part + (size_t)(sg*32)*8192 + b*256 + cs*32 + cl;
    float a = 0.f;
    #pragma unroll 8
    for (int s = 0; s < 32; s++) a += pp[(size_t)s*8192];
    red[tid] = a;
    __syncthreads();
    if (tid < 32) {
        float t = red[tid];
        #pragma unroll
        for (int j = 1; j < 8; j++) t += red[j*32 + tid];
        g_fc1acc[b*256 + cs*32 + tid] = t;
    }
}

// ================= kF: bias+relu, fc2, fc3, tanh =================
__global__ __launch_bounds__(256) void kF(const float* __restrict__ fc1_b, const float* __restrict__ fc2_w,
                   const float* __restrict__ fc2_b, const float* __restrict__ fc3_w,
                   const float* __restrict__ fc3_b, float* __restrict__ out) {
    int b = blockIdx.x; int tid = threadIdx.x;
    __shared__ float s1[256], s2[256];
    s1[tid] = fmaxf(g_fc1acc[b*256 + tid] + fc1_b[tid], 0.f);
    __syncthreads();
    float acc = fc2_b[tid];
    #pragma unroll 8
    for (int k2 = 0; k2 < 256; k2++) acc += s1[k2] * fc2_w[k2*256 + tid];
    s2[tid] = fmaxf(acc, 0.f);
    __syncthreads();
    if (tid < 4) {
        float a3 = fc3_b[tid];
        for (int k2 = 0; k2 < 256; k2++) a3 += s2[k2] * fc3_w[k2*4 + tid];
        out[b*4 + tid] = tanhf(a3);
    }
}

extern "C" void kernel_launch(void* const* d_in, const int* in_sizes, int n_in,
                              void* d_out, int out_size) {
    const float* state     = (const float*)d_in[0];
    const float* W_heads   = (const float*)d_in[1];
    const float* a_src     = (const float*)d_in[2];
    const float* a_dst     = (const float*)d_in[3];
    const float* W_out     = (const float*)d_in[4];
    const float* a_out_src = (const float*)d_in[5];
    const float* a_out_dst = (const float*)d_in[6];
    const float* fc1_w     = (const float*)d_in[7];
    const float* fc1_b     = (const float*)d_in[8];
    const float* fc2_w     = (const float*)d_in[9];
    const float* fc2_b     = (const float*)d_in[10];
    const float* fc3_w     = (const float*)d_in[11];
    const float* fc3_b     = (const float*)d_in[12];
    float* out = (float*)d_out;

    const int SM1 = G1_SMEM_FLOATS * 4;
    const int SM2 = G2_SMEM_FLOATS * 4;
    static int inited = 0;
    if (!inited) {
        cudaFuncSetAttribute(kG1, cudaFuncAttributeMaxDynamicSharedMemorySize, SM1);
        cudaFuncSetAttribute(kG2, cudaFuncAttributeMaxDynamicSharedMemorySize, SM2);
        inited = 1;
    }

    kG1<<<256, 512, SM1>>>(state, W_heads, a_src, a_dst);
    kC <<<dim3(32, 8), 256>>>(W_out, a_out_src, a_out_dst);
    kG2<<<128, 512, SM2>>>();
    kE <<<512, 256>>>(fc1_w);
    kR <<<256, 256>>>();
    kF <<<32, 256>>>(fc1_b, fc2_w, fc2_b, fc3_w, fc3_b, out);
}